// round 11
// baseline (speedup 1.0000x reference)
#include <cuda_runtime.h>
#include <math.h>
#include <stdint.h>

// ---------------- problem constants ----------------
#define BSZ      64
#define T_STEPS  150
#define IN_DIM   120
#define HID      1024
#define OUT_DIM  35
#define NB       8
#define NCOLS    8192          // HID*NB
#define ROWS     9600          // T_STEPS*BSZ
#define TB       32            // (t,b) rows per gemm group (= one ballot word)
#define GROUPS   300           // ROWS/TB
#define NNZ1P    16            // IN_DIM/NB = 15, padded to 16 (pad: idx=0,val=0 -> exact no-op)
#define NNZ2     128           // HID/NB
#define K2_1     8             // NNZ1P/2
#define K2_2     64            // NNZ2/2
#define JT       512           // j-tile per gemm_float block (8 warps x 64 j)
#define XSTR     33            // s_x row stride (conflict-free)

// ---------------- scratch (device globals; no allocation allowed) ----------------
__device__ float    g_D   [(size_t)ROWS * NCOLS];        // dense branch-input buffer (reused per layer)
__device__ unsigned g_bits[(size_t)GROUPS * HID];        // spike bitmasks: [group][i], 32 bits = 32 rows
__device__ float    g_xT  [(size_t)GROUPS * IN_DIM * TB];
__device__ float    g_r   [(size_t)ROWS * OUT_DIM];
__device__ uint4    g_pv1 [K2_1 * NCOLS];                // packed k-pairs (idx0,val0,idx1,val1), [k2][j]; idx prescaled by XSTR
__device__ uint4    g_pv2 [K2_2 * NCOLS];
__device__ uint4    g_pv3 [K2_2 * NCOLS];
__device__ int      g_flag;                              // mask dtype: 0=u8, 1=i32, 2=f32

// ---------------- mask dtype detector ----------------
// Invariant: mask row 0 (layer 1) has exactly 15 ones among IN_DIM=120 entries.
__global__ void detect_mask(const void* m) {
    if (threadIdx.x != 0 || blockIdx.x != 0) return;
    const int*   mi = (const int*)m;
    const float* mf = (const float*)m;
    int  si = 0;   bool oki = true;
    for (int i = 0; i < IN_DIM; i++) { int v = mi[i]; if (v != 0 && v != 1) oki = false; si += v; }
    float sf = 0.f; bool okf = true;
    for (int i = 0; i < IN_DIM; i++) { float v = mf[i]; if (v != 0.f && v != 1.f) okf = false; sf += v; }
    int f = 0;
    if (oki && si == 15) f = 1;
    else if (okf && sf == 15.0f) f = 2;
    g_flag = f;
}

// ---------------- merged CSR build for all 3 layers: warp per output row j ----------------
// `scale` prescales stored idx (layer 1 stores idx*XSTR for direct smem addressing).
__device__ __forceinline__ void build_one(const void* mask, const float* __restrict__ w,
                                          uint2* __restrict__ pv2, int j, int lane,
                                          int sdim, int nnz, int flag, int scale) {
    int base = 0;
    int iters = (sdim + 31) >> 5;
    for (int it = 0; it < iters; it++) {
        int i = it * 32 + lane;
        bool on = false;
        if (i < sdim) {
            if (flag == 1)      on = ((const int*)mask)[(size_t)j * sdim + i] != 0;
            else if (flag == 2) on = ((const float*)mask)[(size_t)j * sdim + i] != 0.f;
            else                on = ((const unsigned char*)mask)[(size_t)j * sdim + i] != 0;
        }
        unsigned bal = __ballot_sync(0xFFFFFFFFu, on);
        if (on) {
            int k = base + __popc(bal & ((1u << lane) - 1u));
            if (k < nnz)
                pv2[2 * ((size_t)(k >> 1) * NCOLS + j) + (k & 1)] =
                    make_uint2((unsigned)(i * scale), __float_as_uint(w[(size_t)j * sdim + i]));
        }
        base += __popc(bal);
    }
    if (lane == 0)
        for (int k = base; k < nnz; k++)
            pv2[2 * ((size_t)(k >> 1) * NCOLS + j) + (k & 1)] = make_uint2(0u, 0u);
}

__global__ void build_all(const void* m1, const float* __restrict__ w1,
                          const void* m2, const float* __restrict__ w2,
                          const void* m3, const float* __restrict__ w3,
                          uint2* pv1, uint2* pv2, uint2* pv3) {
    int gtid  = blockIdx.x * blockDim.x + threadIdx.x;
    int warp  = gtid >> 5;
    int lane  = gtid & 31;
    int layer = warp >> 13;          // NCOLS = 2^13
    int j     = warp & (NCOLS - 1);
    const int f = g_flag;
    if (layer == 0)      build_one(m1, w1, pv1, j, lane, IN_DIM, NNZ1P, f, XSTR);
    else if (layer == 1) build_one(m2, w2, pv2, j, lane, HID,    NNZ2,  f, 1);
    else                 build_one(m3, w3, pv3, j, lane, HID,    NNZ2,  f, 1);
}

// ---------------- transpose x: [b][t][i] -> xT[group][i][row%32] ----------------
__global__ void transpose_x(const float* __restrict__ x, float* __restrict__ xT) {
    int u = blockIdx.x * blockDim.x + threadIdx.x;
    if (u >= ROWS * IN_DIM) return;
    int row = u / IN_DIM;
    int i   = u - row * IN_DIM;
    int t   = row >> 6;
    int b   = row & 63;
    xT[(size_t)(row >> 5) * (IN_DIM * TB) + i * TB + (row & 31)] =
        x[(size_t)(b * T_STEPS + t) * IN_DIM + i];
}

// ---------------- layer-1 gemm: warp-uniform j, lane = row, JT=512 ----------------
// Per (j,k2): 1 uniform LDG.128 (pv) + 2x(IADD+LDS.32 conflict-free+FFMA).
// Results transposed through per-warp smem tiles for coalesced STG.
__global__ __launch_bounds__(256)
void gemm_float(const float* __restrict__ xT, const uint4* __restrict__ pv,
                const float* __restrict__ bias, float* __restrict__ D) {
    extern __shared__ float smem[];
    float* s_x = smem;                       // [IN_DIM][XSTR]   (3960 floats)
    float* s_t = smem + IN_DIM * XSTR;       // 8 warps x [32][33] (8448 floats)

    const int tid  = threadIdx.x;
    const int lane = tid & 31;
    const int warp = tid >> 5;               // 0..7
    const int g    = blockIdx.y;
    const int jb   = blockIdx.x * JT;

    // stage x slice [120][32] -> stride-33
    {
        const float* src = xT + (size_t)g * (IN_DIM * TB);
        for (int u = tid; u < IN_DIM * TB; u += 256)
            s_x[(u >> 5) * XSTR + (u & 31)] = src[u];
    }
    __syncthreads();

    float* s_w = s_t + warp * (32 * 33);

#pragma unroll
    for (int tile = 0; tile < 2; tile++) {
        const int j0 = jb + warp * 64 + tile * 32;
        const float bv_all = bias[j0 + lane];

        for (int jj = 0; jj < 32; jj++) {
            const int j = j0 + jj;
            float a0 = __shfl_sync(0xFFFFFFFFu, bv_all, jj);
            float a1 = 0.f;
            // 8 independent uniform LDG.128 (L2-resident stream), 2 FFMA chains
#pragma unroll
            for (int k2 = 0; k2 < K2_1; k2++) {
                uint4 p = __ldg(&pv[(size_t)k2 * NCOLS + j]);
                a0 += __uint_as_float(p.y) * s_x[p.x + lane];
                a1 += __uint_as_float(p.w) * s_x[p.z + lane];
            }
            s_w[jj * 33 + lane] = a0 + a1;
        }
        __syncwarp();
        // coalesced writeout: for each row r, lane=jj reads s_w[lane*33+r] (conflict-free)
#pragma unroll 4
        for (int r = 0; r < 32; r++)
            D[(size_t)(g * TB + r) * NCOLS + j0 + lane] = s_w[lane * 33 + r];
        __syncwarp();
    }
}

// ---------------- layer-2/3 gemm (binary spike input, 32-bit mask path) ----------------
__global__ __launch_bounds__(256, 2)
void gemm_bits(const unsigned* __restrict__ bitsIn, const uint4* __restrict__ pv,
               const float* __restrict__ bias, float* __restrict__ D) {
    __shared__ unsigned s_bits[HID];
    const int tid = threadIdx.x;
    const int g   = blockIdx.y;

    const unsigned* src = bitsIn + (size_t)g * HID;
    for (int u = tid; u < HID; u += 256) s_bits[u] = src[u];
    __syncthreads();

    const int j0 = blockIdx.x * 512 + tid;
    float acc[2][32];
#pragma unroll
    for (int c = 0; c < 2; c++) {
        float bv = bias[j0 + c * 256];
#pragma unroll
        for (int r = 0; r < 32; r++) acc[c][r] = bv;
    }

    uint4 nx[2];
    nx[0] = pv[j0]; nx[1] = pv[j0 + 256];

#pragma unroll 1
    for (int k2 = 0; k2 < K2_2; k2++) {
        uint4 cur[2];
        cur[0] = nx[0]; cur[1] = nx[1];
        if (k2 + 1 < K2_2) {
            nx[0] = pv[(size_t)(k2 + 1) * NCOLS + j0];
            nx[1] = pv[(size_t)(k2 + 1) * NCOLS + j0 + 256];
        }
#pragma unroll
        for (int c = 0; c < 2; c++) {
            unsigned m0 = s_bits[cur[c].x];
            float    v0 = __uint_as_float(cur[c].y);
            unsigned m1 = s_bits[cur[c].z];
            float    v1 = __uint_as_float(cur[c].w);
#pragma unroll
            for (int r = 0; r < 32; r++)
                if (m0 & (1u << r)) acc[c][r] += v0;
#pragma unroll
            for (int r = 0; r < 32; r++)
                if (m1 & (1u << r)) acc[c][r] += v1;
        }
    }

#pragma unroll
    for (int c = 0; c < 2; c++)
#pragma unroll
        for (int r = 0; r < 32; r++)
            D[(size_t)(g * TB + r) * NCOLS + j0 + c * 256] = acc[c][r];
}

// ---------------- scan producing spike BITMASKS (all 3 layers) ----------------
__global__ __launch_bounds__(256)
void scan_bits(const float* __restrict__ D, const float* __restrict__ tau_m,
               const float* __restrict__ tau_n, unsigned* __restrict__ bitsOut) {
    int tid  = blockIdx.x * 256 + threadIdx.x;      // 0 .. 65535
    int h    = tid >> 6;
    int b    = tid & 63;
    int lane = threadIdx.x & 31;

    float beta[8], omb[8];
#pragma unroll
    for (int n = 0; n < 8; n++) {
        float bb = 1.f / (1.f + expf(-tau_n[h * 8 + n]));
        beta[n] = bb; omb[n] = 1.f - bb;
    }
    float alpha = 1.f / (1.f + expf(-tau_m[h]));
    float oma   = 1.f - alpha;

    float d[8];
#pragma unroll
    for (int n = 0; n < 8; n++) d[n] = 0.f;
    float mem = 0.f, spk = 0.f;

    const float* base = D + (size_t)h * 8;
    float4 n0 = *(const float4*)(base + (size_t)b * NCOLS);
    float4 n1 = *(const float4*)(base + (size_t)b * NCOLS + 4);

    for (int t = 0; t < T_STEPS; t++) {
        float4 q0 = n0, q1 = n1;
        if (t + 1 < T_STEPS) {
            size_t roff = (size_t)((t + 1) * 64 + b) * NCOLS;
            n0 = *(const float4*)(base + roff);
            n1 = *(const float4*)(base + roff + 4);
        }
        d[0] = beta[0] * d[0] + omb[0] * q0.x;
        d[1] = beta[1] * d[1] + omb[1] * q0.y;
        d[2] = beta[2] * d[2] + omb[2] * q0.z;
        d[3] = beta[3] * d[3] + omb[3] * q0.w;
        d[4] = beta[4] * d[4] + omb[4] * q1.x;
        d[5] = beta[5] * d[5] + omb[5] * q1.y;
        d[6] = beta[6] * d[6] + omb[6] * q1.z;
        d[7] = beta[7] * d[7] + omb[7] * q1.w;
        float l = ((d[0] + d[1]) + (d[2] + d[3])) + ((d[4] + d[5]) + (d[6] + d[7]));
        mem = mem * alpha + oma * l - spk;
        bool fired = mem > 1.0f;
        spk = fired ? 1.0f : 0.0f;
        unsigned bal = __ballot_sync(0xFFFFFFFFu, fired);
        if (lane == 0) {
            int grp = (t * 64 + b) >> 5;             // == t*2 + (b>=32)
            bitsOut[(size_t)grp * HID + h] = bal;
        }
    }
}

// ---------------- readout from spike bitmasks ----------------
#define RO_THREADS 280          // 35 o x 8 chunks
__global__ __launch_bounds__(RO_THREADS)
void readout_bits(const unsigned* __restrict__ bitsIn, const float* __restrict__ wr,
                  const float* __restrict__ br, float* __restrict__ rOut) {
    __shared__ unsigned s_bits[HID];
    __shared__ float    s_red[RO_THREADS * 32];
    const int tid = threadIdx.x;
    const int g   = blockIdx.x;

    const unsigned* src = bitsIn + (size_t)g * HID;
    for (int u = tid; u < HID; u += RO_THREADS) s_bits[u] = src[u];
    __syncthreads();

    const int o     = tid >> 3;          // 0..34
    const int chunk = tid & 7;           // 0..7
    float acc[32];
#pragma unroll
    for (int r = 0; r < 32; r++) acc[r] = 0.f;

    const float* wrow = wr + o * HID + chunk * 128;
    const unsigned* mb = s_bits + chunk * 128;
#pragma unroll 4
    for (int i = 0; i < 128; i++) {
        unsigned m = mb[i];
        float    v = wrow[i];
#pragma unroll
        for (int r = 0; r < 32; r++)
            if (m & (1u << r)) acc[r] += v;
    }
#pragma unroll
    for (int r = 0; r < 32; r++) s_red[tid * 32 + r] = acc[r];
    __syncthreads();

    for (int u = tid; u < OUT_DIM * 32; u += RO_THREADS) {
        int oo  = u >> 5;
        int row = u & 31;
        float s = br[oo];
#pragma unroll
        for (int c = 0; c < 8; c++)
            s += s_red[(oo * 8 + c) * 32 + row];
        rOut[(size_t)(g * TB + row) * OUT_DIM + oo] = s;
    }
}

// ---------------- readout leaky scan + mean + log_softmax ----------------
__global__ void final_k(const float* __restrict__ rIn, const float* __restrict__ tau_mr,
                        float* __restrict__ out) {
    int b = blockIdx.x;
    int o = threadIdx.x;                     // blockDim = 64, only o<35 active
    __shared__ float sv[64];
    __shared__ float s_mx, s_ls;
    float acc = 0.f;
    if (o < OUT_DIM) {
        float alpha = 1.f / (1.f + expf(-tau_mr[o]));
        float oma = 1.f - alpha;
        float mr = 0.f;
        for (int t = 0; t < T_STEPS; t++) {
            mr = mr * alpha + oma * rIn[(size_t)(t * 64 + b) * OUT_DIM + o];
            acc += mr;
        }
        acc /= (float)T_STEPS;
    }
    sv[o] = (o < OUT_DIM) ? acc : -1e30f;
    __syncthreads();
    if (o == 0) {
        float m = -1e30f;
        for (int i = 0; i < OUT_DIM; i++) m = fmaxf(m, sv[i]);
        float s = 0.f;
        for (int i = 0; i < OUT_DIM; i++) s += expf(sv[i] - m);
        s_mx = m; s_ls = logf(s);
    }
    __syncthreads();
    if (o < OUT_DIM) out[b * OUT_DIM + o] = sv[o] - s_mx - s_ls;
}

// ---------------- launch ----------------
extern "C" void kernel_launch(void* const* d_in, const int* in_sizes, int n_in,
                              void* d_out, int out_size) {
    (void)in_sizes; (void)n_in; (void)out_size;
    const float* x   = (const float*)d_in[0];
    const float* w1  = (const float*)d_in[1];
    const float* b1  = (const float*)d_in[2];
    const float* tm1 = (const float*)d_in[3];
    const float* tn1 = (const float*)d_in[4];
    const float* w2  = (const float*)d_in[5];
    const float* b2  = (const float*)d_in[6];
    const float* tm2 = (const float*)d_in[7];
    const float* tn2 = (const float*)d_in[8];
    const float* w3  = (const float*)d_in[9];
    const float* b3  = (const float*)d_in[10];
    const float* tm3 = (const float*)d_in[11];
    const float* tn3 = (const float*)d_in[12];
    const float* wr  = (const float*)d_in[13];
    const float* br  = (const float*)d_in[14];
    const float* tmr = (const float*)d_in[15];
    const void*  m1  = d_in[16];
    const void*  m2  = d_in[17];
    const void*  m3  = d_in[18];
    float* out = (float*)d_out;

    void *pD, *pB, *pxT, *pr, *pv1, *pv2, *pv3;
    cudaGetSymbolAddress(&pD,  g_D);
    cudaGetSymbolAddress(&pB,  g_bits);
    cudaGetSymbolAddress(&pxT, g_xT);
    cudaGetSymbolAddress(&pr,  g_r);
    cudaGetSymbolAddress(&pv1, g_pv1);
    cudaGetSymbolAddress(&pv2, g_pv2);
    cudaGetSymbolAddress(&pv3, g_pv3);

    const int gf_smem = (IN_DIM * XSTR + 8 * 32 * 33) * 4;   // 49,632 B
    cudaFuncSetAttribute(gemm_float, cudaFuncAttributeMaxDynamicSharedMemorySize, gf_smem);

    // 1) mask dtype + merged CSR build
    detect_mask<<<1, 32>>>(m1);
    build_all<<<3 * NCOLS * 32 / 256, 256>>>(m1, w1, m2, w2, m3, w3,
                                             (uint2*)pv1, (uint2*)pv2, (uint2*)pv3);

    // 2) input transpose
    transpose_x<<<(ROWS * IN_DIM + 255) / 256, 256>>>(x, (float*)pxT);

    dim3 gf(NCOLS / JT, GROUPS);
    dim3 gb(NCOLS / 512, GROUPS);

    // 3) layer 1 (float input, warp-uniform j, JT=512) -> spike bitmasks
    gemm_float<<<gf, 256, gf_smem>>>((const float*)pxT, (const uint4*)pv1, b1, (float*)pD);
    scan_bits<<<(BSZ * HID) / 256, 256>>>((const float*)pD, tm1, tn1, (unsigned*)pB);

    // 4) layer 2 (bitmask input) -> spike bitmasks
    gemm_bits<<<gb, 256>>>((const unsigned*)pB, (const uint4*)pv2, b2, (float*)pD);
    scan_bits<<<(BSZ * HID) / 256, 256>>>((const float*)pD, tm2, tn2, (unsigned*)pB);

    // 5) layer 3 (bitmask input) -> spike bitmasks
    gemm_bits<<<gb, 256>>>((const unsigned*)pB, (const uint4*)pv3, b3, (float*)pD);
    scan_bits<<<(BSZ * HID) / 256, 256>>>((const float*)pD, tm3, tn3, (unsigned*)pB);

    // 6) readout from bits + final scan + log_softmax
    readout_bits<<<GROUPS, RO_THREADS>>>((const unsigned*)pB, wr, br, (float*)pr);
    final_k<<<BSZ, 64>>>((const float*)pr, tmr, out);
}

// round 12
// speedup vs baseline: 1.0448x; 1.0448x over previous
#include <cuda_runtime.h>
#include <math.h>
#include <stdint.h>

// ---------------- problem constants ----------------
#define BSZ      64
#define T_STEPS  150
#define IN_DIM   120
#define HID      1024
#define OUT_DIM  35
#define NB       8
#define NCOLS    8192          // HID*NB
#define ROWS     9600          // T_STEPS*BSZ
#define TB       32            // (t,b) rows per gemm group (= one ballot word)
#define GROUPS   300           // ROWS/TB
#define NNZ1P    16            // IN_DIM/NB = 15, padded to 16 (pad: idx=0,val=0 -> exact no-op)
#define NNZ2     128           // HID/NB
#define K2_1     8             // NNZ1P/2
#define K2_2     64            // NNZ2/2
#define XSTR     33            // s_x row stride in floats (conflict-free)
#define XSCALE   (XSTR * 4)    // idx prescale for layer 1: byte offset of row idx

// D layout (NEW): [group][j][32 rows]  -> coalesced for gemm_float stores AND scan reads
__device__ float    g_D   [(size_t)ROWS * NCOLS];
__device__ unsigned g_bits[(size_t)GROUPS * HID];        // spike bitmasks: [group][i], bit r = row r
__device__ float    g_xT  [(size_t)GROUPS * IN_DIM * TB];
__device__ float    g_r   [(size_t)ROWS * OUT_DIM];
__device__ uint4    g_pv1 [NCOLS * K2_1];                // layer 1: [j][k2], idx prescaled to BYTE offsets
__device__ uint4    g_pv2 [K2_2 * NCOLS];                // layers 2/3: [k2][j]
__device__ uint4    g_pv3 [K2_2 * NCOLS];

// ---------------- merged prep: mask-dtype detect + CSR build + x transpose ----------------
// Invariant: mask row 0 (layer 1) has exactly 15 ones among IN_DIM=120 entries.
__device__ __forceinline__ int mask_flag(const void* m1, int lane) {
    int  si = 0;   bool oki = true;
    float sf = 0.f; bool okf = true;
#pragma unroll
    for (int it = 0; it < 4; it++) {
        int i = it * 32 + lane;
        if (i < IN_DIM) {
            int v = ((const int*)m1)[i];
            if (v != 0 && v != 1) oki = false;
            si += v;
            float f = ((const float*)m1)[i];
            if (f != 0.f && f != 1.f) okf = false;
            sf += f;
        }
    }
#pragma unroll
    for (int s = 16; s > 0; s >>= 1) {
        si += __shfl_xor_sync(0xFFFFFFFFu, si, s);
        sf += __shfl_xor_sync(0xFFFFFFFFu, sf, s);
    }
    oki = __all_sync(0xFFFFFFFFu, oki);
    okf = __all_sync(0xFFFFFFFFu, okf);
    if (oki && si == 15) return 1;
    if (okf && sf == 15.0f) return 2;
    return 0;
}

// layout=0: layer1 [j][k] uint2 slots (idx scaled by XSCALE); layout=1: [k2][j] pairs.
__device__ __forceinline__ void build_one(const void* mask, const float* __restrict__ w,
                                          uint2* __restrict__ pv2, int j, int lane,
                                          int sdim, int nnz, int flag, int scale, int layout) {
    int base = 0;
    int iters = (sdim + 31) >> 5;
    for (int it = 0; it < iters; it++) {
        int i = it * 32 + lane;
        bool on = false;
        if (i < sdim) {
            if (flag == 1)      on = ((const int*)mask)[(size_t)j * sdim + i] != 0;
            else if (flag == 2) on = ((const float*)mask)[(size_t)j * sdim + i] != 0.f;
            else                on = ((const unsigned char*)mask)[(size_t)j * sdim + i] != 0;
        }
        unsigned bal = __ballot_sync(0xFFFFFFFFu, on);
        if (on) {
            int k = base + __popc(bal & ((1u << lane) - 1u));
            if (k < nnz) {
                size_t slot = layout ? (2 * ((size_t)(k >> 1) * NCOLS + j) + (k & 1))
                                     : ((size_t)j * nnz + k);
                pv2[slot] = make_uint2((unsigned)(i * scale),
                                       __float_as_uint(w[(size_t)j * sdim + i]));
            }
        }
        base += __popc(bal);
    }
    if (lane == 0)
        for (int k = base; k < nnz; k++) {
            size_t slot = layout ? (2 * ((size_t)(k >> 1) * NCOLS + j) + (k & 1))
                                 : ((size_t)j * nnz + k);
            pv2[slot] = make_uint2(0u, 0u);
        }
}

#define BUILD_BLOCKS (3 * NCOLS / 8)      // 3072 (8 warps per block)
#define TRANS_BLOCKS ((ROWS * IN_DIM + 255) / 256)

__global__ void prep_all(const float* __restrict__ x, float* __restrict__ xT,
                         const void* m1, const float* __restrict__ w1,
                         const void* m2, const float* __restrict__ w2,
                         const void* m3, const float* __restrict__ w3,
                         uint2* pv1, uint2* pv2, uint2* pv3) {
    if (blockIdx.x < BUILD_BLOCKS) {
        int warp = blockIdx.x * 8 + (threadIdx.x >> 5);
        int lane = threadIdx.x & 31;
        int layer = warp >> 13;              // NCOLS = 2^13
        int j     = warp & (NCOLS - 1);
        int f = mask_flag(m1, lane);
        if (layer == 0)      build_one(m1, w1, pv1, j, lane, IN_DIM, NNZ1P, f, XSCALE, 0);
        else if (layer == 1) build_one(m2, w2, pv2, j, lane, HID,    NNZ2,  f, 1,      1);
        else                 build_one(m3, w3, pv3, j, lane, HID,    NNZ2,  f, 1,      1);
    } else {
        int u = (blockIdx.x - BUILD_BLOCKS) * 256 + threadIdx.x;
        if (u >= ROWS * IN_DIM) return;
        int row = u / IN_DIM;
        int i   = u - row * IN_DIM;
        int t   = row >> 6;
        int b   = row & 63;
        xT[(size_t)(row >> 5) * (IN_DIM * TB) + i * TB + (row & 31)] =
            x[(size_t)(b * T_STEPS + t) * IN_DIM + i];
    }
}

// ---------------- layer-1 gemm: warp-uniform j, lane = row, direct coalesced store ----------------
// Per j: 8 uniform LDG.128 (pv, contiguous [j][k2]) + bias + 16 conflict-free LDS + 16 FFMA + 1 STG.
__global__ __launch_bounds__(256)
void gemm_float(const float* __restrict__ xT, const uint4* __restrict__ pv,
                const float* __restrict__ bias, float* __restrict__ D) {
    __shared__ float s_x[IN_DIM * XSTR];
    const int tid  = threadIdx.x;
    const int lane = tid & 31;
    const int warp = tid >> 5;
    const int g    = blockIdx.y;
    const int j0   = blockIdx.x * 512 + warp * 64;

    {
        const float* src = xT + (size_t)g * (IN_DIM * TB);
        for (int u = tid; u < IN_DIM * TB; u += 256)
            s_x[(u >> 5) * XSTR + (u & 31)] = src[u];
    }
    __syncthreads();

    const char* xbase = (const char*)s_x + lane * 4;    // idx already in byte units
    float* dlane = D + (size_t)g * NCOLS * 32 + lane;

#pragma unroll 1
    for (int jj = 0; jj < 64; jj += 2) {
        const int ja = j0 + jj;
        const int jb = ja + 1;
        const uint4* pa = pv + (size_t)ja * K2_1;
        const uint4* pb = pv + (size_t)jb * K2_1;
        uint4 A[8], B[8];
#pragma unroll
        for (int k = 0; k < 8; k++) { A[k] = __ldg(pa + k); B[k] = __ldg(pb + k); }
        float a0 = __ldg(bias + ja), a1 = 0.f;
        float b0 = __ldg(bias + jb), b1 = 0.f;
#pragma unroll
        for (int k = 0; k < 8; k++) {
            a0 += __uint_as_float(A[k].y) * *(const float*)(xbase + A[k].x);
            a1 += __uint_as_float(A[k].w) * *(const float*)(xbase + A[k].z);
            b0 += __uint_as_float(B[k].y) * *(const float*)(xbase + B[k].x);
            b1 += __uint_as_float(B[k].w) * *(const float*)(xbase + B[k].z);
        }
        dlane[(size_t)ja * 32] = a0 + a1;
        dlane[(size_t)jb * 32] = b0 + b1;
    }
}

// ---------------- layer-2/3 gemm (binary spike input, 32-bit mask path) ----------------
__global__ __launch_bounds__(256, 2)
void gemm_bits(const unsigned* __restrict__ bitsIn, const uint4* __restrict__ pv,
               const float* __restrict__ bias, float* __restrict__ D) {
    __shared__ unsigned s_bits[HID];
    const int tid = threadIdx.x;
    const int g   = blockIdx.y;

    const unsigned* src = bitsIn + (size_t)g * HID;
    for (int u = tid; u < HID; u += 256) s_bits[u] = src[u];
    __syncthreads();

    const int j0 = blockIdx.x * 512 + tid;
    float acc[2][32];
#pragma unroll
    for (int c = 0; c < 2; c++) {
        float bv = bias[j0 + c * 256];
#pragma unroll
        for (int r = 0; r < 32; r++) acc[c][r] = bv;
    }

    uint4 nx[2];
    nx[0] = pv[j0]; nx[1] = pv[j0 + 256];

#pragma unroll 1
    for (int k2 = 0; k2 < K2_2; k2++) {
        uint4 cur[2];
        cur[0] = nx[0]; cur[1] = nx[1];
        if (k2 + 1 < K2_2) {
            nx[0] = pv[(size_t)(k2 + 1) * NCOLS + j0];
            nx[1] = pv[(size_t)(k2 + 1) * NCOLS + j0 + 256];
        }
#pragma unroll
        for (int c = 0; c < 2; c++) {
            unsigned m0 = s_bits[cur[c].x];
            float    v0 = __uint_as_float(cur[c].y);
            unsigned m1 = s_bits[cur[c].z];
            float    v1 = __uint_as_float(cur[c].w);
#pragma unroll
            for (int r = 0; r < 32; r++)
                if (m0 & (1u << r)) acc[c][r] += v0;
#pragma unroll
            for (int r = 0; r < 32; r++)
                if (m1 & (1u << r)) acc[c][r] += v1;
        }
    }

    // store: D[g][j][0..31] contiguous per thread (8 x STG.128)
#pragma unroll
    for (int c = 0; c < 2; c++) {
        float* dst = D + ((size_t)g * NCOLS + j0 + c * 256) * 32;
#pragma unroll
        for (int q = 0; q < 8; q++)
            *(float4*)(dst + q * 4) = make_float4(acc[c][q*4], acc[c][q*4+1],
                                                  acc[c][q*4+2], acc[c][q*4+3]);
    }
}

// ---------------- scan producing spike BITMASKS (all 3 layers) ----------------
// Warp = fixed h, 32 consecutive b. Reads D[g][h*8+n][lane] -> coalesced 128B per n.
__global__ __launch_bounds__(256)
void scan_bits(const float* __restrict__ D, const float* __restrict__ tau_m,
               const float* __restrict__ tau_n, unsigned* __restrict__ bitsOut) {
    int tid  = blockIdx.x * 256 + threadIdx.x;      // 0 .. 65535
    int h    = tid >> 6;
    int b    = tid & 63;
    int hi   = b >> 5;                               // warp-uniform
    int lane = threadIdx.x & 31;                     // == b & 31

    float beta[8], omb[8];
#pragma unroll
    for (int n = 0; n < 8; n++) {
        float bb = 1.f / (1.f + expf(-tau_n[h * 8 + n]));
        beta[n] = bb; omb[n] = 1.f - bb;
    }
    float alpha = 1.f / (1.f + expf(-tau_m[h]));
    float oma   = 1.f - alpha;

    float d[8];
#pragma unroll
    for (int n = 0; n < 8; n++) d[n] = 0.f;
    float mem = 0.f, spk = 0.f;

    const size_t tstride = (size_t)2 * NCOLS * 32;   // per-t stride in floats
    const float* dbase = D + ((size_t)hi * NCOLS + h * 8) * 32 + lane;

    float cur[8], nxt[8];
#pragma unroll
    for (int n = 0; n < 8; n++) cur[n] = dbase[n * 32];

    for (int t = 0; t < T_STEPS; t++) {
        if (t + 1 < T_STEPS) {
            const float* p = dbase + (size_t)(t + 1) * tstride;
#pragma unroll
            for (int n = 0; n < 8; n++) nxt[n] = p[n * 32];
        }
        float l = 0.f;
#pragma unroll
        for (int n = 0; n < 8; n++) {
            d[n] = beta[n] * d[n] + omb[n] * cur[n];
        }
        l = ((d[0] + d[1]) + (d[2] + d[3])) + ((d[4] + d[5]) + (d[6] + d[7]));
        mem = mem * alpha + oma * l - spk;
        bool fired = mem > 1.0f;
        spk = fired ? 1.0f : 0.0f;
        unsigned bal = __ballot_sync(0xFFFFFFFFu, fired);
        if (lane == 0)
            bitsOut[(size_t)(t * 2 + hi) * HID + h] = bal;
#pragma unroll
        for (int n = 0; n < 8; n++) cur[n] = nxt[n];
    }
}

// ---------------- readout from spike bitmasks ----------------
#define RO_THREADS 280          // 35 o x 8 chunks
__global__ __launch_bounds__(RO_THREADS)
void readout_bits(const unsigned* __restrict__ bitsIn, const float* __restrict__ wr,
                  const float* __restrict__ br, float* __restrict__ rOut) {
    __shared__ unsigned s_bits[HID];
    __shared__ float    s_red[RO_THREADS * 32];
    const int tid = threadIdx.x;
    const int g   = blockIdx.x;

    const unsigned* src = bitsIn + (size_t)g * HID;
    for (int u = tid; u < HID; u += RO_THREADS) s_bits[u] = src[u];
    __syncthreads();

    const int o     = tid >> 3;          // 0..34
    const int chunk = tid & 7;           // 0..7
    float acc[32];
#pragma unroll
    for (int r = 0; r < 32; r++) acc[r] = 0.f;

    const float* wrow = wr + o * HID + chunk * 128;
    const unsigned* mb = s_bits + chunk * 128;
#pragma unroll 4
    for (int i = 0; i < 128; i++) {
        unsigned m = mb[i];
        float    v = wrow[i];
#pragma unroll
        for (int r = 0; r < 32; r++)
            if (m & (1u << r)) acc[r] += v;
    }
#pragma unroll
    for (int r = 0; r < 32; r++) s_red[tid * 32 + r] = acc[r];
    __syncthreads();

    for (int u = tid; u < OUT_DIM * 32; u += RO_THREADS) {
        int oo  = u >> 5;
        int row = u & 31;
        float s = br[oo];
#pragma unroll
        for (int c = 0; c < 8; c++)
            s += s_red[(oo * 8 + c) * 32 + row];
        rOut[(size_t)(g * TB + row) * OUT_DIM + oo] = s;
    }
}

// ---------------- readout leaky scan + mean + log_softmax ----------------
__global__ void final_k(const float* __restrict__ rIn, const float* __restrict__ tau_mr,
                        float* __restrict__ out) {
    int b = blockIdx.x;
    int o = threadIdx.x;                     // blockDim = 64, only o<35 active
    __shared__ float sv[64];
    __shared__ float s_mx, s_ls;
    float acc = 0.f;
    if (o < OUT_DIM) {
        float alpha = 1.f / (1.f + expf(-tau_mr[o]));
        float oma = 1.f - alpha;
        float mr = 0.f;
        for (int t = 0; t < T_STEPS; t++) {
            mr = mr * alpha + oma * rIn[(size_t)(t * 64 + b) * OUT_DIM + o];
            acc += mr;
        }
        acc /= (float)T_STEPS;
    }
    sv[o] = (o < OUT_DIM) ? acc : -1e30f;
    __syncthreads();
    if (o == 0) {
        float m = -1e30f;
        for (int i = 0; i < OUT_DIM; i++) m = fmaxf(m, sv[i]);
        float s = 0.f;
        for (int i = 0; i < OUT_DIM; i++) s += expf(sv[i] - m);
        s_mx = m; s_ls = logf(s);
    }
    __syncthreads();
    if (o < OUT_DIM) out[b * OUT_DIM + o] = sv[o] - s_mx - s_ls;
}

// ---------------- launch ----------------
extern "C" void kernel_launch(void* const* d_in, const int* in_sizes, int n_in,
                              void* d_out, int out_size) {
    (void)in_sizes; (void)n_in; (void)out_size;
    const float* x   = (const float*)d_in[0];
    const float* w1  = (const float*)d_in[1];
    const float* b1  = (const float*)d_in[2];
    const float* tm1 = (const float*)d_in[3];
    const float* tn1 = (const float*)d_in[4];
    const float* w2  = (const float*)d_in[5];
    const float* b2  = (const float*)d_in[6];
    const float* tm2 = (const float*)d_in[7];
    const float* tn2 = (const float*)d_in[8];
    const float* w3  = (const float*)d_in[9];
    const float* b3  = (const float*)d_in[10];
    const float* tm3 = (const float*)d_in[11];
    const float* tn3 = (const float*)d_in[12];
    const float* wr  = (const float*)d_in[13];
    const float* br  = (const float*)d_in[14];
    const float* tmr = (const float*)d_in[15];
    const void*  m1  = d_in[16];
    const void*  m2  = d_in[17];
    const void*  m3  = d_in[18];
    float* out = (float*)d_out;

    void *pD, *pB, *pxT, *pr, *pv1, *pv2, *pv3;
    cudaGetSymbolAddress(&pD,  g_D);
    cudaGetSymbolAddress(&pB,  g_bits);
    cudaGetSymbolAddress(&pxT, g_xT);
    cudaGetSymbolAddress(&pr,  g_r);
    cudaGetSymbolAddress(&pv1, g_pv1);
    cudaGetSymbolAddress(&pv2, g_pv2);
    cudaGetSymbolAddress(&pv3, g_pv3);

    // 1) merged prep: dtype detect + CSR build (3 layers) + x transpose
    prep_all<<<BUILD_BLOCKS + TRANS_BLOCKS, 256>>>(
        x, (float*)pxT, m1, w1, m2, w2, m3, w3,
        (uint2*)pv1, (uint2*)pv2, (uint2*)pv3);

    dim3 gf(NCOLS / 512, GROUPS);
    dim3 gb(NCOLS / 512, GROUPS);

    // 2) layer 1 (float input, warp-uniform j, coalesced store) -> spike bitmasks
    gemm_float<<<gf, 256>>>((const float*)pxT, (const uint4*)pv1, b1, (float*)pD);
    scan_bits<<<(BSZ * HID) / 256, 256>>>((const float*)pD, tm1, tn1, (unsigned*)pB);

    // 3) layer 2 (bitmask input) -> spike bitmasks
    gemm_bits<<<gb, 256>>>((const unsigned*)pB, (const uint4*)pv2, b2, (float*)pD);
    scan_bits<<<(BSZ * HID) / 256, 256>>>((const float*)pD, tm2, tn2, (unsigned*)pB);

    // 4) layer 3 (bitmask input) -> spike bitmasks
    gemm_bits<<<gb, 256>>>((const unsigned*)pB, (const uint4*)pv3, b3, (float*)pD);
    scan_bits<<<(BSZ * HID) / 256, 256>>>((const float*)pD, tm3, tn3, (unsigned*)pB);

    // 5) readout from bits + final scan + log_softmax
    readout_bits<<<GROUPS, RO_THREADS>>>((const unsigned*)pB, wr, br, (float*)pr);
    final_k<<<BSZ, 64>>>((const float*)pr, tmr, out);
}

// round 13
// speedup vs baseline: 1.0774x; 1.0312x over previous
#include <cuda_runtime.h>
#include <math.h>
#include <stdint.h>

// ---------------- problem constants ----------------
#define BSZ      64
#define T_STEPS  150
#define IN_DIM   120
#define HID      1024
#define OUT_DIM  35
#define NB       8
#define NCOLS    8192          // HID*NB
#define ROWS     9600          // T_STEPS*BSZ
#define TB       32            // (t,b) rows per gemm group (= one ballot word)
#define GROUPS   300           // ROWS/TB
#define NNZ1P    16            // IN_DIM/NB = 15, padded to 16 (pad: idx=0,val=0 -> exact no-op)
#define NNZ2     128           // HID/NB
#define K2_1     8             // NNZ1P/2
#define K2_2     64            // NNZ2/2
#define XSTR     33            // s_x row stride in floats (conflict-free)
#define XSCALE   (XSTR * 4)    // idx prescale for layer 1: byte offset of row idx

// D layout: [group][j][32 rows]  -> coalesced for gemm stores AND scan reads
__device__ float    g_D   [(size_t)ROWS * NCOLS];
__device__ unsigned g_bits[(size_t)GROUPS * HID];        // spike bitmasks: [group][i], bit r = row r
__device__ float    g_xT  [(size_t)GROUPS * IN_DIM * TB];
__device__ float    g_r   [(size_t)ROWS * OUT_DIM];
__device__ uint4    g_pv1 [NCOLS * K2_1];                // layer 1: [j][k2], idx prescaled to BYTE offsets
__device__ uint4    g_pv2 [K2_2 * NCOLS];                // layers 2/3: [k2][j]
__device__ uint4    g_pv3 [K2_2 * NCOLS];

// ---------------- merged prep: mask-dtype detect + CSR build + x transpose ----------------
__device__ __forceinline__ int mask_flag(const void* m1, int lane) {
    int  si = 0;   bool oki = true;
    float sf = 0.f; bool okf = true;
#pragma unroll
    for (int it = 0; it < 4; it++) {
        int i = it * 32 + lane;
        if (i < IN_DIM) {
            int v = ((const int*)m1)[i];
            if (v != 0 && v != 1) oki = false;
            si += v;
            float f = ((const float*)m1)[i];
            if (f != 0.f && f != 1.f) okf = false;
            sf += f;
        }
    }
#pragma unroll
    for (int s = 16; s > 0; s >>= 1) {
        si += __shfl_xor_sync(0xFFFFFFFFu, si, s);
        sf += __shfl_xor_sync(0xFFFFFFFFu, sf, s);
    }
    oki = __all_sync(0xFFFFFFFFu, oki);
    okf = __all_sync(0xFFFFFFFFu, okf);
    if (oki && si == 15) return 1;
    if (okf && sf == 15.0f) return 2;
    return 0;
}

// layout=0: layer1 [j][k] uint2 slots (idx scaled by XSCALE); layout=1: [k2][j] pairs.
__device__ __forceinline__ void build_one(const void* mask, const float* __restrict__ w,
                                          uint2* __restrict__ pv2, int j, int lane,
                                          int sdim, int nnz, int flag, int scale, int layout) {
    int base = 0;
    int iters = (sdim + 31) >> 5;
    for (int it = 0; it < iters; it++) {
        int i = it * 32 + lane;
        bool on = false;
        if (i < sdim) {
            if (flag == 1)      on = ((const int*)mask)[(size_t)j * sdim + i] != 0;
            else if (flag == 2) on = ((const float*)mask)[(size_t)j * sdim + i] != 0.f;
            else                on = ((const unsigned char*)mask)[(size_t)j * sdim + i] != 0;
        }
        unsigned bal = __ballot_sync(0xFFFFFFFFu, on);
        if (on) {
            int k = base + __popc(bal & ((1u << lane) - 1u));
            if (k < nnz) {
                size_t slot = layout ? (2 * ((size_t)(k >> 1) * NCOLS + j) + (k & 1))
                                     : ((size_t)j * nnz + k);
                pv2[slot] = make_uint2((unsigned)(i * scale),
                                       __float_as_uint(w[(size_t)j * sdim + i]));
            }
        }
        base += __popc(bal);
    }
    if (lane == 0)
        for (int k = base; k < nnz; k++) {
            size_t slot = layout ? (2 * ((size_t)(k >> 1) * NCOLS + j) + (k & 1))
                                 : ((size_t)j * nnz + k);
            pv2[slot] = make_uint2(0u, 0u);
        }
}

#define BUILD_BLOCKS (3 * NCOLS / 8)      // 3072 (8 warps per block)
#define TRANS_BLOCKS ((ROWS * IN_DIM + 255) / 256)

__global__ void prep_all(const float* __restrict__ x, float* __restrict__ xT,
                         const void* m1, const float* __restrict__ w1,
                         const void* m2, const float* __restrict__ w2,
                         const void* m3, const float* __restrict__ w3,
                         uint2* pv1, uint2* pv2, uint2* pv3) {
    if (blockIdx.x < BUILD_BLOCKS) {
        int warp = blockIdx.x * 8 + (threadIdx.x >> 5);
        int lane = threadIdx.x & 31;
        int layer = warp >> 13;              // NCOLS = 2^13
        int j     = warp & (NCOLS - 1);
        int f = mask_flag(m1, lane);
        if (layer == 0)      build_one(m1, w1, pv1, j, lane, IN_DIM, NNZ1P, f, XSCALE, 0);
        else if (layer == 1) build_one(m2, w2, pv2, j, lane, HID,    NNZ2,  f, 1,      1);
        else                 build_one(m3, w3, pv3, j, lane, HID,    NNZ2,  f, 1,      1);
    } else {
        int u = (blockIdx.x - BUILD_BLOCKS) * 256 + threadIdx.x;
        if (u >= ROWS * IN_DIM) return;
        int row = u / IN_DIM;
        int i   = u - row * IN_DIM;
        int t   = row >> 6;
        int b   = row & 63;
        xT[(size_t)(row >> 5) * (IN_DIM * TB) + i * TB + (row & 31)] =
            x[(size_t)(b * T_STEPS + t) * IN_DIM + i];
    }
}

// ---------------- layer-1 gemm: warp-uniform j, lane = row, direct coalesced store ----------------
__global__ __launch_bounds__(256)
void gemm_float(const float* __restrict__ xT, const uint4* __restrict__ pv,
                const float* __restrict__ bias, float* __restrict__ D) {
    __shared__ float s_x[IN_DIM * XSTR];
    const int tid  = threadIdx.x;
    const int lane = tid & 31;
    const int warp = tid >> 5;
    const int g    = blockIdx.y;
    const int j0   = blockIdx.x * 512 + warp * 64;

    {
        const float* src = xT + (size_t)g * (IN_DIM * TB);
        for (int u = tid; u < IN_DIM * TB; u += 256)
            s_x[(u >> 5) * XSTR + (u & 31)] = src[u];
    }
    __syncthreads();

    const char* xbase = (const char*)s_x + lane * 4;    // idx already in byte units
    float* dlane = D + (size_t)g * NCOLS * 32 + lane;

#pragma unroll 1
    for (int jj = 0; jj < 64; jj += 2) {
        const int ja = j0 + jj;
        const int jb = ja + 1;
        const uint4* pa = pv + (size_t)ja * K2_1;
        const uint4* pb = pv + (size_t)jb * K2_1;
        uint4 A[8], B[8];
#pragma unroll
        for (int k = 0; k < 8; k++) { A[k] = __ldg(pa + k); B[k] = __ldg(pb + k); }
        float a0 = __ldg(bias + ja), a1 = 0.f;
        float b0 = __ldg(bias + jb), b1 = 0.f;
#pragma unroll
        for (int k = 0; k < 8; k++) {
            a0 += __uint_as_float(A[k].y) * *(const float*)(xbase + A[k].x);
            a1 += __uint_as_float(A[k].w) * *(const float*)(xbase + A[k].z);
            b0 += __uint_as_float(B[k].y) * *(const float*)(xbase + B[k].x);
            b1 += __uint_as_float(B[k].w) * *(const float*)(xbase + B[k].z);
        }
        dlane[(size_t)ja * 32] = a0 + a1;
        dlane[(size_t)jb * 32] = b0 + b1;
    }
}

// ---------------- layer-2/3 gemm (binary spike input, 32-bit mask path) ----------------
// One j per thread; 2-deep pipeline: pv prefetched 2 k2 ahead (LDG), masks 1 k2 ahead (LDS).
__global__ __launch_bounds__(256)
void gemm_bits(const unsigned* __restrict__ bitsIn, const uint4* __restrict__ pv,
               const float* __restrict__ bias, float* __restrict__ D) {
    __shared__ unsigned s_bits[HID];
    const int tid = threadIdx.x;
    const int g   = blockIdx.y;

    const unsigned* src = bitsIn + (size_t)g * HID;
    for (int u = tid; u < HID; u += 256) s_bits[u] = src[u];
    __syncthreads();

    const int j0 = blockIdx.x * 256 + tid;
    float acc[32];
    {
        float bv = bias[j0];
#pragma unroll
        for (int r = 0; r < 32; r++) acc[r] = bv;
    }

    // pipeline primer: p0 = k2 (current), p1 = k2+1; masks for p0 gathered.
    uint4 p0 = pv[j0];
    uint4 p1 = pv[(size_t)1 * NCOLS + j0];
    unsigned m0 = s_bits[p0.x];
    unsigned m1 = s_bits[p0.z];

#pragma unroll 1
    for (int k2 = 0; k2 < K2_2; k2++) {
        // prefetch pv k2+2 (long LDG latency covered by this iteration's FADDs)
        uint4 p2;
        if (k2 + 2 < K2_2) p2 = pv[(size_t)(k2 + 2) * NCOLS + j0];
        // gather masks for k2+1 from the already-arrived p1 (LDS latency covered too)
        unsigned m0n = 0, m1n = 0;
        if (k2 + 1 < K2_2) { m0n = s_bits[p1.x]; m1n = s_bits[p1.z]; }

        const float v0 = __uint_as_float(p0.y);
        const float v1 = __uint_as_float(p0.w);
#pragma unroll
        for (int r = 0; r < 32; r++)
            if (m0 & (1u << r)) acc[r] += v0;
#pragma unroll
        for (int r = 0; r < 32; r++)
            if (m1 & (1u << r)) acc[r] += v1;

        p0 = p1; p1 = p2; m0 = m0n; m1 = m1n;
    }

    // store: D[g][j][0..31] contiguous per thread (8 x STG.128)
    float* dst = D + ((size_t)g * NCOLS + j0) * 32;
#pragma unroll
    for (int q = 0; q < 8; q++)
        *(float4*)(dst + q * 4) = make_float4(acc[q*4], acc[q*4+1], acc[q*4+2], acc[q*4+3]);
}

// ---------------- scan producing spike BITMASKS (all 3 layers) ----------------
__global__ __launch_bounds__(256)
void scan_bits(const float* __restrict__ D, const float* __restrict__ tau_m,
               const float* __restrict__ tau_n, unsigned* __restrict__ bitsOut) {
    int tid  = blockIdx.x * 256 + threadIdx.x;      // 0 .. 65535
    int h    = tid >> 6;
    int b    = tid & 63;
    int hi   = b >> 5;                               // warp-uniform
    int lane = threadIdx.x & 31;                     // == b & 31

    float beta[8], omb[8];
#pragma unroll
    for (int n = 0; n < 8; n++) {
        float bb = 1.f / (1.f + expf(-tau_n[h * 8 + n]));
        beta[n] = bb; omb[n] = 1.f - bb;
    }
    float alpha = 1.f / (1.f + expf(-tau_m[h]));
    float oma   = 1.f - alpha;

    float d[8];
#pragma unroll
    for (int n = 0; n < 8; n++) d[n] = 0.f;
    float mem = 0.f, spk = 0.f;

    const size_t tstride = (size_t)2 * NCOLS * 32;   // per-t stride in floats
    const float* dbase = D + ((size_t)hi * NCOLS + h * 8) * 32 + lane;

    float cur[8], nxt[8];
#pragma unroll
    for (int n = 0; n < 8; n++) cur[n] = dbase[n * 32];

    for (int t = 0; t < T_STEPS; t++) {
        if (t + 1 < T_STEPS) {
            const float* p = dbase + (size_t)(t + 1) * tstride;
#pragma unroll
            for (int n = 0; n < 8; n++) nxt[n] = p[n * 32];
        }
#pragma unroll
        for (int n = 0; n < 8; n++)
            d[n] = beta[n] * d[n] + omb[n] * cur[n];
        float l = ((d[0] + d[1]) + (d[2] + d[3])) + ((d[4] + d[5]) + (d[6] + d[7]));
        mem = mem * alpha + oma * l - spk;
        bool fired = mem > 1.0f;
        spk = fired ? 1.0f : 0.0f;
        unsigned bal = __ballot_sync(0xFFFFFFFFu, fired);
        if (lane == 0)
            bitsOut[(size_t)(t * 2 + hi) * HID + h] = bal;
#pragma unroll
        for (int n = 0; n < 8; n++) cur[n] = nxt[n];
    }
}

// ---------------- readout from spike bitmasks ----------------
#define RO_THREADS 280          // 35 o x 8 chunks
__global__ __launch_bounds__(RO_THREADS)
void readout_bits(const unsigned* __restrict__ bitsIn, const float* __restrict__ wr,
                  const float* __restrict__ br, float* __restrict__ rOut) {
    __shared__ unsigned s_bits[HID];
    __shared__ float    s_red[RO_THREADS * 32];
    const int tid = threadIdx.x;
    const int g   = blockIdx.x;

    const unsigned* src = bitsIn + (size_t)g * HID;
    for (int u = tid; u < HID; u += RO_THREADS) s_bits[u] = src[u];
    __syncthreads();

    const int o     = tid >> 3;          // 0..34
    const int chunk = tid & 7;           // 0..7
    float acc[32];
#pragma unroll
    for (int r = 0; r < 32; r++) acc[r] = 0.f;

    const float* wrow = wr + o * HID + chunk * 128;
    const unsigned* mb = s_bits + chunk * 128;
#pragma unroll 4
    for (int i = 0; i < 128; i++) {
        unsigned m = mb[i];
        float    v = wrow[i];
#pragma unroll
        for (int r = 0; r < 32; r++)
            if (m & (1u << r)) acc[r] += v;
    }
#pragma unroll
    for (int r = 0; r < 32; r++) s_red[tid * 32 + r] = acc[r];
    __syncthreads();

    for (int u = tid; u < OUT_DIM * 32; u += RO_THREADS) {
        int oo  = u >> 5;
        int row = u & 31;
        float s = br[oo];
#pragma unroll
        for (int c = 0; c < 8; c++)
            s += s_red[(oo * 8 + c) * 32 + row];
        rOut[(size_t)(g * TB + row) * OUT_DIM + oo] = s;
    }
}

// ---------------- readout leaky scan + mean + log_softmax ----------------
__global__ void final_k(const float* __restrict__ rIn, const float* __restrict__ tau_mr,
                        float* __restrict__ out) {
    int b = blockIdx.x;
    int o = threadIdx.x;                     // blockDim = 64, only o<35 active
    __shared__ float sv[64];
    __shared__ float s_mx, s_ls;
    float acc = 0.f;
    if (o < OUT_DIM) {
        float alpha = 1.f / (1.f + expf(-tau_mr[o]));
        float oma = 1.f - alpha;
        float mr = 0.f;
        for (int t = 0; t < T_STEPS; t++) {
            mr = mr * alpha + oma * rIn[(size_t)(t * 64 + b) * OUT_DIM + o];
            acc += mr;
        }
        acc /= (float)T_STEPS;
    }
    sv[o] = (o < OUT_DIM) ? acc : -1e30f;
    __syncthreads();
    if (o == 0) {
        float m = -1e30f;
        for (int i = 0; i < OUT_DIM; i++) m = fmaxf(m, sv[i]);
        float s = 0.f;
        for (int i = 0; i < OUT_DIM; i++) s += expf(sv[i] - m);
        s_mx = m; s_ls = logf(s);
    }
    __syncthreads();
    if (o < OUT_DIM) out[b * OUT_DIM + o] = sv[o] - s_mx - s_ls;
}

// ---------------- launch ----------------
extern "C" void kernel_launch(void* const* d_in, const int* in_sizes, int n_in,
                              void* d_out, int out_size) {
    (void)in_sizes; (void)n_in; (void)out_size;
    const float* x   = (const float*)d_in[0];
    const float* w1  = (const float*)d_in[1];
    const float* b1  = (const float*)d_in[2];
    const float* tm1 = (const float*)d_in[3];
    const float* tn1 = (const float*)d_in[4];
    const float* w2  = (const float*)d_in[5];
    const float* b2  = (const float*)d_in[6];
    const float* tm2 = (const float*)d_in[7];
    const float* tn2 = (const float*)d_in[8];
    const float* w3  = (const float*)d_in[9];
    const float* b3  = (const float*)d_in[10];
    const float* tm3 = (const float*)d_in[11];
    const float* tn3 = (const float*)d_in[12];
    const float* wr  = (const float*)d_in[13];
    const float* br  = (const float*)d_in[14];
    const float* tmr = (const float*)d_in[15];
    const void*  m1  = d_in[16];
    const void*  m2  = d_in[17];
    const void*  m3  = d_in[18];
    float* out = (float*)d_out;

    void *pD, *pB, *pxT, *pr, *pv1, *pv2, *pv3;
    cudaGetSymbolAddress(&pD,  g_D);
    cudaGetSymbolAddress(&pB,  g_bits);
    cudaGetSymbolAddress(&pxT, g_xT);
    cudaGetSymbolAddress(&pr,  g_r);
    cudaGetSymbolAddress(&pv1, g_pv1);
    cudaGetSymbolAddress(&pv2, g_pv2);
    cudaGetSymbolAddress(&pv3, g_pv3);

    // 1) merged prep: dtype detect + CSR build (3 layers) + x transpose
    prep_all<<<BUILD_BLOCKS + TRANS_BLOCKS, 256>>>(
        x, (float*)pxT, m1, w1, m2, w2, m3, w3,
        (uint2*)pv1, (uint2*)pv2, (uint2*)pv3);

    dim3 gf(NCOLS / 512, GROUPS);
    dim3 gb(NCOLS / 256, GROUPS);

    // 2) layer 1 (float input, warp-uniform j, coalesced store) -> spike bitmasks
    gemm_float<<<gf, 256>>>((const float*)pxT, (const uint4*)pv1, b1, (float*)pD);
    scan_bits<<<(BSZ * HID) / 256, 256>>>((const float*)pD, tm1, tn1, (unsigned*)pB);

    // 3) layer 2 (bitmask input) -> spike bitmasks
    gemm_bits<<<gb, 256>>>((const unsigned*)pB, (const uint4*)pv2, b2, (float*)pD);
    scan_bits<<<(BSZ * HID) / 256, 256>>>((const float*)pD, tm2, tn2, (unsigned*)pB);

    // 4) layer 3 (bitmask input) -> spike bitmasks
    gemm_bits<<<gb, 256>>>((const unsigned*)pB, (const uint4*)pv3, b3, (float*)pD);
    scan_bits<<<(BSZ * HID) / 256, 256>>>((const float*)pD, tm3, tn3, (unsigned*)pB);

    // 5) readout from bits + final scan + log_softmax
    readout_bits<<<GROUPS, RO_THREADS>>>((const unsigned*)pB, wr, br, (float*)pr);
    final_k<<<BSZ, 64>>>((const float*)pr, tmr, out);
}

// round 14
// speedup vs baseline: 1.3044x; 1.2106x over previous
#include <cuda_runtime.h>
#include <math.h>
#include <stdint.h>

// ---------------- problem constants ----------------
#define BSZ      64
#define T_STEPS  150
#define IN_DIM   120
#define HID      1024
#define OUT_DIM  35
#define NB       8
#define NCOLS    8192          // HID*NB
#define ROWS     9600          // T_STEPS*BSZ
#define TB       32            // (t,b) rows per gemm group (= one ballot word)
#define GROUPS   300           // ROWS/TB
#define NNZ1P    16            // IN_DIM/NB = 15, padded to 16 (pad: idx=0,val=0 -> exact no-op)
#define NNZ2     128           // HID/NB
#define K2_1     8             // NNZ1P/2
#define K2_2     64            // NNZ2/2
#define XSTR     33            // s_x row stride in floats (conflict-free)
#define XSCALE   (XSTR * 4)    // idx prescale for layer 1: byte offset of row idx

// D layout: [group][j][32 rows]  -> coalesced for gemm stores AND scan reads
__device__ float    g_D   [(size_t)ROWS * NCOLS];
__device__ unsigned g_bits[(size_t)GROUPS * HID];        // spike bitmasks: [group][i], bit r = row r
__device__ float    g_xT  [(size_t)GROUPS * IN_DIM * TB];
__device__ float    g_r   [(size_t)ROWS * OUT_DIM];
__device__ uint4    g_pv1 [NCOLS * K2_1];                // layer 1: [j][k2], idx prescaled to BYTE offsets
__device__ uint4    g_pv2 [K2_2 * NCOLS];                // layers 2/3: [k2][j]
__device__ uint4    g_pv3 [K2_2 * NCOLS];

// ---------------- merged prep: mask-dtype detect + CSR build + x transpose ----------------
__device__ __forceinline__ int mask_flag(const void* m1, int lane) {
    int  si = 0;   bool oki = true;
    float sf = 0.f; bool okf = true;
#pragma unroll
    for (int it = 0; it < 4; it++) {
        int i = it * 32 + lane;
        if (i < IN_DIM) {
            int v = ((const int*)m1)[i];
            if (v != 0 && v != 1) oki = false;
            si += v;
            float f = ((const float*)m1)[i];
            if (f != 0.f && f != 1.f) okf = false;
            sf += f;
        }
    }
#pragma unroll
    for (int s = 16; s > 0; s >>= 1) {
        si += __shfl_xor_sync(0xFFFFFFFFu, si, s);
        sf += __shfl_xor_sync(0xFFFFFFFFu, sf, s);
    }
    oki = __all_sync(0xFFFFFFFFu, oki);
    okf = __all_sync(0xFFFFFFFFu, okf);
    if (oki && si == 15) return 1;
    if (okf && sf == 15.0f) return 2;
    return 0;
}

// layout=0: layer1 [j][k] uint2 slots (idx scaled by XSCALE); layout=1: [k2][j] pairs.
__device__ __forceinline__ void build_one(const void* mask, const float* __restrict__ w,
                                          uint2* __restrict__ pv2, int j, int lane,
                                          int sdim, int nnz, int flag, int scale, int layout) {
    int base = 0;
    int iters = (sdim + 31) >> 5;
    for (int it = 0; it < iters; it++) {
        int i = it * 32 + lane;
        bool on = false;
        if (i < sdim) {
            if (flag == 1)      on = ((const int*)mask)[(size_t)j * sdim + i] != 0;
            else if (flag == 2) on = ((const float*)mask)[(size_t)j * sdim + i] != 0.f;
            else                on = ((const unsigned char*)mask)[(size_t)j * sdim + i] != 0;
        }
        unsigned bal = __ballot_sync(0xFFFFFFFFu, on);
        if (on) {
            int k = base + __popc(bal & ((1u << lane) - 1u));
            if (k < nnz) {
                size_t slot = layout ? (2 * ((size_t)(k >> 1) * NCOLS + j) + (k & 1))
                                     : ((size_t)j * nnz + k);
                pv2[slot] = make_uint2((unsigned)(i * scale),
                                       __float_as_uint(w[(size_t)j * sdim + i]));
            }
        }
        base += __popc(bal);
    }
    if (lane == 0)
        for (int k = base; k < nnz; k++) {
            size_t slot = layout ? (2 * ((size_t)(k >> 1) * NCOLS + j) + (k & 1))
                                 : ((size_t)j * nnz + k);
            pv2[slot] = make_uint2(0u, 0u);
        }
}

#define BUILD_BLOCKS (3 * NCOLS / 8)      // 3072 (8 warps per block)
#define TRANS_BLOCKS ((ROWS * IN_DIM + 255) / 256)

__global__ void prep_all(const float* __restrict__ x, float* __restrict__ xT,
                         const void* m1, const float* __restrict__ w1,
                         const void* m2, const float* __restrict__ w2,
                         const void* m3, const float* __restrict__ w3,
                         uint2* pv1, uint2* pv2, uint2* pv3) {
    if (blockIdx.x < BUILD_BLOCKS) {
        int warp = blockIdx.x * 8 + (threadIdx.x >> 5);
        int lane = threadIdx.x & 31;
        int layer = warp >> 13;              // NCOLS = 2^13
        int j     = warp & (NCOLS - 1);
        int f = mask_flag(m1, lane);
        if (layer == 0)      build_one(m1, w1, pv1, j, lane, IN_DIM, NNZ1P, f, XSCALE, 0);
        else if (layer == 1) build_one(m2, w2, pv2, j, lane, HID,    NNZ2,  f, 1,      1);
        else                 build_one(m3, w3, pv3, j, lane, HID,    NNZ2,  f, 1,      1);
    } else {
        int u = (blockIdx.x - BUILD_BLOCKS) * 256 + threadIdx.x;
        if (u >= ROWS * IN_DIM) return;
        int row = u / IN_DIM;
        int i   = u - row * IN_DIM;
        int t   = row >> 6;
        int b   = row & 63;
        xT[(size_t)(row >> 5) * (IN_DIM * TB) + i * TB + (row & 31)] =
            x[(size_t)(b * T_STEPS + t) * IN_DIM + i];
    }
}

// ---------------- layer-1 gemm: warp-uniform j, lane = row, ping-pong j prefetch ----------------
__global__ __launch_bounds__(256)
void gemm_float(const float* __restrict__ xT, const uint4* __restrict__ pv,
                const float* __restrict__ bias, float* __restrict__ D) {
    __shared__ float s_x[IN_DIM * XSTR];
    const int tid  = threadIdx.x;
    const int lane = tid & 31;
    const int warp = tid >> 5;
    const int g    = blockIdx.y;
    const int j0   = blockIdx.x * 512 + warp * 64;

    {
        const float* src = xT + (size_t)g * (IN_DIM * TB);
        for (int u = tid; u < IN_DIM * TB; u += 256)
            s_x[(u >> 5) * XSTR + (u & 31)] = src[u];
    }
    __syncthreads();

    const char* xbase = (const char*)s_x + lane * 4;    // idx already in byte units
    float* dlane = D + ((size_t)g * NCOLS + j0) * 32 + lane;
    const uint4* p = pv + (size_t)j0 * K2_1;            // 64*8 contiguous uint4 stream

    // preload j = 0 of this warp's range
    uint4 A[8], B[8];
#pragma unroll
    for (int k = 0; k < 8; k++) A[k] = __ldg(p + k);
    float bva = __ldg(bias + j0);

#pragma unroll 1
    for (int jj = 0; jj < 64; jj += 2) {
        // prefetch j = jj+1 into B while A is processed
#pragma unroll
        for (int k = 0; k < 8; k++) B[k] = __ldg(p + (jj + 1) * 8 + k);
        float bvb = __ldg(bias + j0 + jj + 1);

        float a0 = bva, a1 = 0.f;
#pragma unroll
        for (int k = 0; k < 8; k++) {
            a0 += __uint_as_float(A[k].y) * *(const float*)(xbase + A[k].x);
            a1 += __uint_as_float(A[k].w) * *(const float*)(xbase + A[k].z);
        }
        dlane[(size_t)jj * 32] = a0 + a1;

        // prefetch j = jj+2 into A while B is processed (clamped; tail load unused)
        const int jn = (jj + 2 < 64) ? (jj + 2) : 0;
#pragma unroll
        for (int k = 0; k < 8; k++) A[k] = __ldg(p + jn * 8 + k);
        bva = __ldg(bias + j0 + jn);

        float b0 = bvb, b1 = 0.f;
#pragma unroll
        for (int k = 0; k < 8; k++) {
            b0 += __uint_as_float(B[k].y) * *(const float*)(xbase + B[k].x);
            b1 += __uint_as_float(B[k].w) * *(const float*)(xbase + B[k].z);
        }
        dlane[(size_t)(jj + 1) * 32] = b0 + b1;
    }
}

// ---------------- layer-2/3 gemm: static 4-slot ring, zero-MOV pipeline ----------------
// Entry e (= k2) holds (idx0,val0,idx1,val1). Process order identical to prior rounds.
#define ADDS(MASK, V)                                   \
    _Pragma("unroll")                                   \
    for (int r = 0; r < 32; r++)                        \
        if ((MASK) & (1u << r)) acc[r] += (V);

__global__ __launch_bounds__(256)
void gemm_bits(const unsigned* __restrict__ bitsIn, const uint4* __restrict__ pv,
               const float* __restrict__ bias, float* __restrict__ D) {
    __shared__ unsigned s_bits[HID];
    const int tid = threadIdx.x;
    const int g   = blockIdx.y;

    const unsigned* src = bitsIn + (size_t)g * HID;
    for (int u = tid; u < HID; u += 256) s_bits[u] = src[u];
    __syncthreads();

    const int j0 = blockIdx.x * 256 + tid;
    float acc[32];
    {
        float bv = bias[j0];
#pragma unroll
        for (int r = 0; r < 32; r++) acc[r] = bv;
    }

    const uint4* base = pv + j0;
    uint4 s0 = base[(size_t)0 * NCOLS];
    uint4 s1 = base[(size_t)1 * NCOLS];
    uint4 s2 = base[(size_t)2 * NCOLS];
    uint4 s3 = base[(size_t)3 * NCOLS];
    unsigned mA0 = s_bits[s0.x], mA1 = s_bits[s0.z];
    unsigned mB0, mB1;

#pragma unroll 1
    for (int i = 0; i < K2_2; i += 4) {
        // sub0: entry i (slot s0), cur masks mA; gather mB from s1 (entry i+1)
        mB0 = s_bits[s1.x];  mB1 = s_bits[s1.z];
        {
            const float v0 = __uint_as_float(s0.y);
            const float v1 = __uint_as_float(s0.w);
            s0 = base[(size_t)min(i + 4, K2_2 - 1) * NCOLS];    // prefetch entry i+4
            ADDS(mA0, v0);
            ADDS(mA1, v1);
        }
        // sub1: entry i+1 (s1), cur mB; gather mA from s2
        mA0 = s_bits[s2.x];  mA1 = s_bits[s2.z];
        {
            const float v0 = __uint_as_float(s1.y);
            const float v1 = __uint_as_float(s1.w);
            s1 = base[(size_t)min(i + 5, K2_2 - 1) * NCOLS];
            ADDS(mB0, v0);
            ADDS(mB1, v1);
        }
        // sub2: entry i+2 (s2), cur mA; gather mB from s3
        mB0 = s_bits[s3.x];  mB1 = s_bits[s3.z];
        {
            const float v0 = __uint_as_float(s2.y);
            const float v1 = __uint_as_float(s2.w);
            s2 = base[(size_t)min(i + 6, K2_2 - 1) * NCOLS];
            ADDS(mA0, v0);
            ADDS(mA1, v1);
        }
        // sub3: entry i+3 (s3), cur mB; gather mA from s0 (now holds entry i+4)
        mA0 = s_bits[s0.x];  mA1 = s_bits[s0.z];
        {
            const float v0 = __uint_as_float(s3.y);
            const float v1 = __uint_as_float(s3.w);
            s3 = base[(size_t)min(i + 7, K2_2 - 1) * NCOLS];
            ADDS(mB0, v0);
            ADDS(mB1, v1);
        }
    }

    // store: D[g][j][0..31] contiguous per thread (8 x STG.128)
    float* dst = D + ((size_t)g * NCOLS + j0) * 32;
#pragma unroll
    for (int q = 0; q < 8; q++)
        *(float4*)(dst + q * 4) = make_float4(acc[q*4], acc[q*4+1], acc[q*4+2], acc[q*4+3]);
}

// ---------------- scan producing spike BITMASKS: 6-slot rolling prefetch ----------------
// Warp = fixed h, 32 consecutive b. 150 = 6 x 25.
__global__ __launch_bounds__(128)
void scan_bits(const float* __restrict__ D, const float* __restrict__ tau_m,
               const float* __restrict__ tau_n, unsigned* __restrict__ bitsOut) {
    int tid  = blockIdx.x * 128 + threadIdx.x;      // 0 .. 65535
    int h    = tid >> 6;
    int b    = tid & 63;
    int hi   = b >> 5;                               // warp-uniform
    int lane = threadIdx.x & 31;                     // == b & 31

    float beta[8], omb[8];
#pragma unroll
    for (int n = 0; n < 8; n++) {
        float bb = 1.f / (1.f + expf(-tau_n[h * 8 + n]));
        beta[n] = bb; omb[n] = 1.f - bb;
    }
    float alpha = 1.f / (1.f + expf(-tau_m[h]));
    float oma   = 1.f - alpha;

    float d[8];
#pragma unroll
    for (int n = 0; n < 8; n++) d[n] = 0.f;
    float mem = 0.f, spk = 0.f;

    const size_t tstride = (size_t)2 * NCOLS * 32;   // per-t stride in floats
    const float* dbase = D + ((size_t)hi * NCOLS + h * 8) * 32 + lane;

    float S[6][8];
#pragma unroll
    for (int s = 0; s < 6; s++) {
        const float* p = dbase + (size_t)s * tstride;
#pragma unroll
        for (int n = 0; n < 8; n++) S[s][n] = p[n * 32];
    }

#pragma unroll 1
    for (int i = 0; i < 25; i++) {
        const int t0 = i * 6;
#pragma unroll
        for (int s = 0; s < 6; s++) {
            const int t = t0 + s;
            // consume slot s, then refill with t+6 (clamped; tail loads unused)
#pragma unroll
            for (int n = 0; n < 8; n++)
                d[n] = beta[n] * d[n] + omb[n] * S[s][n];
            {
                const int tp = (t + 6 < T_STEPS) ? (t + 6) : t;
                const float* p = dbase + (size_t)tp * tstride;
#pragma unroll
                for (int n = 0; n < 8; n++) S[s][n] = p[n * 32];
            }
            float l = ((d[0] + d[1]) + (d[2] + d[3])) + ((d[4] + d[5]) + (d[6] + d[7]));
            mem = mem * alpha + oma * l - spk;
            bool fired = mem > 1.0f;
            spk = fired ? 1.0f : 0.0f;
            unsigned bal = __ballot_sync(0xFFFFFFFFu, fired);
            if (lane == 0)
                bitsOut[(size_t)(t * 2 + hi) * HID + h] = bal;
        }
    }
}

// ---------------- readout from spike bitmasks ----------------
#define RO_THREADS 280          // 35 o x 8 chunks
__global__ __launch_bounds__(RO_THREADS)
void readout_bits(const unsigned* __restrict__ bitsIn, const float* __restrict__ wr,
                  const float* __restrict__ br, float* __restrict__ rOut) {
    __shared__ unsigned s_bits[HID];
    __shared__ float    s_red[RO_THREADS * 32];
    const int tid = threadIdx.x;
    const int g   = blockIdx.x;

    const unsigned* src = bitsIn + (size_t)g * HID;
    for (int u = tid; u < HID; u += RO_THREADS) s_bits[u] = src[u];
    __syncthreads();

    const int o     = tid >> 3;          // 0..34
    const int chunk = tid & 7;           // 0..7
    float acc[32];
#pragma unroll
    for (int r = 0; r < 32; r++) acc[r] = 0.f;

    const float* wrow = wr + o * HID + chunk * 128;
    const unsigned* mb = s_bits + chunk * 128;
#pragma unroll 4
    for (int i = 0; i < 128; i++) {
        unsigned m = mb[i];
        float    v = wrow[i];
#pragma unroll
        for (int r = 0; r < 32; r++)
            if (m & (1u << r)) acc[r] += v;
    }
#pragma unroll
    for (int r = 0; r < 32; r++) s_red[tid * 32 + r] = acc[r];
    __syncthreads();

    for (int u = tid; u < OUT_DIM * 32; u += RO_THREADS) {
        int oo  = u >> 5;
        int row = u & 31;
        float s = br[oo];
#pragma unroll
        for (int c = 0; c < 8; c++)
            s += s_red[(oo * 8 + c) * 32 + row];
        rOut[(size_t)(g * TB + row) * OUT_DIM + oo] = s;
    }
}

// ---------------- readout leaky scan + mean + log_softmax ----------------
__global__ void final_k(const float* __restrict__ rIn, const float* __restrict__ tau_mr,
                        float* __restrict__ out) {
    int b = blockIdx.x;
    int o = threadIdx.x;                     // blockDim = 64, only o<35 active
    __shared__ float sv[64];
    __shared__ float s_mx, s_ls;
    float acc = 0.f;
    if (o < OUT_DIM) {
        float alpha = 1.f / (1.f + expf(-tau_mr[o]));
        float oma = 1.f - alpha;
        float mr = 0.f;
        for (int t = 0; t < T_STEPS; t++) {
            mr = mr * alpha + oma * rIn[(size_t)(t * 64 + b) * OUT_DIM + o];
            acc += mr;
        }
        acc /= (float)T_STEPS;
    }
    sv[o] = (o < OUT_DIM) ? acc : -1e30f;
    __syncthreads();
    if (o == 0) {
        float m = -1e30f;
        for (int i = 0; i < OUT_DIM; i++) m = fmaxf(m, sv[i]);
        float s = 0.f;
        for (int i = 0; i < OUT_DIM; i++) s += expf(sv[i] - m);
        s_mx = m; s_ls = logf(s);
    }
    __syncthreads();
    if (o < OUT_DIM) out[b * OUT_DIM + o] = sv[o] - s_mx - s_ls;
}

// ---------------- launch ----------------
extern "C" void kernel_launch(void* const* d_in, const int* in_sizes, int n_in,
                              void* d_out, int out_size) {
    (void)in_sizes; (void)n_in; (void)out_size;
    const float* x   = (const float*)d_in[0];
    const float* w1  = (const float*)d_in[1];
    const float* b1  = (const float*)d_in[2];
    const float* tm1 = (const float*)d_in[3];
    const float* tn1 = (const float*)d_in[4];
    const float* w2  = (const float*)d_in[5];
    const float* b2  = (const float*)d_in[6];
    const float* tm2 = (const float*)d_in[7];
    const float* tn2 = (const float*)d_in[8];
    const float* w3  = (const float*)d_in[9];
    const float* b3  = (const float*)d_in[10];
    const float* tm3 = (const float*)d_in[11];
    const float* tn3 = (const float*)d_in[12];
    const float* wr  = (const float*)d_in[13];
    const float* br  = (const float*)d_in[14];
    const float* tmr = (const float*)d_in[15];
    const void*  m1  = d_in[16];
    const void*  m2  = d_in[17];
    const void*  m3  = d_in[18];
    float* out = (float*)d_out;

    void *pD, *pB, *pxT, *pr, *pv1, *pv2, *pv3;
    cudaGetSymbolAddress(&pD,  g_D);
    cudaGetSymbolAddress(&pB,  g_bits);
    cudaGetSymbolAddress(&pxT, g_xT);
    cudaGetSymbolAddress(&pr,  g_r);
    cudaGetSymbolAddress(&pv1, g_pv1);
    cudaGetSymbolAddress(&pv2, g_pv2);
    cudaGetSymbolAddress(&pv3, g_pv3);

    // 1) merged prep: dtype detect + CSR build (3 layers) + x transpose
    prep_all<<<BUILD_BLOCKS + TRANS_BLOCKS, 256>>>(
        x, (float*)pxT, m1, w1, m2, w2, m3, w3,
        (uint2*)pv1, (uint2*)pv2, (uint2*)pv3);

    dim3 gf(NCOLS / 512, GROUPS);
    dim3 gb(NCOLS / 256, GROUPS);
    const int scan_blocks = (BSZ * HID) / 128;

    // 2) layer 1 (float input) -> spike bitmasks
    gemm_float<<<gf, 256>>>((const float*)pxT, (const uint4*)pv1, b1, (float*)pD);
    scan_bits<<<scan_blocks, 128>>>((const float*)pD, tm1, tn1, (unsigned*)pB);

    // 3) layer 2 (bitmask input) -> spike bitmasks
    gemm_bits<<<gb, 256>>>((const unsigned*)pB, (const uint4*)pv2, b2, (float*)pD);
    scan_bits<<<scan_blocks, 128>>>((const float*)pD, tm2, tn2, (unsigned*)pB);

    // 4) layer 3 (bitmask input) -> spike bitmasks
    gemm_bits<<<gb, 256>>>((const unsigned*)pB, (const uint4*)pv3, b3, (float*)pD);
    scan_bits<<<scan_blocks, 128>>>((const float*)pD, tm3, tn3, (unsigned*)pB);

    // 5) readout from bits + final scan + log_softmax
    readout_bits<<<GROUPS, RO_THREADS>>>((const unsigned*)pB, wr, br, (float*)pr);
    final_k<<<BSZ, 64>>>((const float*)pr, tmr, out);
}

// round 15
// speedup vs baseline: 2.2952x; 1.7596x over previous
#include <cuda_runtime.h>
#include <math.h>
#include <stdint.h>

// ---------------- problem constants ----------------
#define BSZ      64
#define T_STEPS  150
#define IN_DIM   120
#define HID      1024
#define OUT_DIM  35
#define NB       8
#define NCOLS    8192          // HID*NB
#define ROWS     9600          // T_STEPS*BSZ
#define TB       32            // (t,b) rows per gemm group (= one ballot word)
#define GROUPS   300           // ROWS/TB
#define NNZ1P    16            // IN_DIM/NB = 15, padded to 16 (pad: idx=0,val=0 -> exact no-op)
#define NNZ2     128           // HID/NB
#define K2_1     8             // NNZ1P/2
#define K2_2     64            // NNZ2/2
#define XSTR     33            // s_x row stride in floats (conflict-free)
#define XSCALE   (XSTR * 4)    // idx prescale for layer 1: byte offset of row idx

// D layout: [group][j][32 rows]  -> coalesced for gemm stores AND scan reads
__device__ float    g_D   [(size_t)ROWS * NCOLS];
__device__ unsigned g_bits[(size_t)GROUPS * HID];        // spike bitmasks: [group][i], bit r = row r
__device__ float    g_xT  [(size_t)GROUPS * IN_DIM * TB];
__device__ float    g_r   [(size_t)ROWS * OUT_DIM];
__device__ uint4    g_pv1 [NCOLS * K2_1];                // layer 1: [j][k2], idx prescaled to BYTE offsets
__device__ uint4    g_pv2 [K2_2 * NCOLS];                // layers 2/3: [k2][j]
__device__ uint4    g_pv3 [K2_2 * NCOLS];
__device__ int      g_nz  [3 * GROUPS];                  // per-(layer,group) any-spike flags

// ---------------- merged prep: mask-dtype detect + CSR build + x transpose + flag zero ----------------
__device__ __forceinline__ int mask_flag(const void* m1, int lane) {
    int  si = 0;   bool oki = true;
    float sf = 0.f; bool okf = true;
#pragma unroll
    for (int it = 0; it < 4; it++) {
        int i = it * 32 + lane;
        if (i < IN_DIM) {
            int v = ((const int*)m1)[i];
            if (v != 0 && v != 1) oki = false;
            si += v;
            float f = ((const float*)m1)[i];
            if (f != 0.f && f != 1.f) okf = false;
            sf += f;
        }
    }
#pragma unroll
    for (int s = 16; s > 0; s >>= 1) {
        si += __shfl_xor_sync(0xFFFFFFFFu, si, s);
        sf += __shfl_xor_sync(0xFFFFFFFFu, sf, s);
    }
    oki = __all_sync(0xFFFFFFFFu, oki);
    okf = __all_sync(0xFFFFFFFFu, okf);
    if (oki && si == 15) return 1;
    if (okf && sf == 15.0f) return 2;
    return 0;
}

// layout=0: layer1 [j][k] uint2 slots (idx scaled by XSCALE); layout=1: [k2][j] pairs.
__device__ __forceinline__ void build_one(const void* mask, const float* __restrict__ w,
                                          uint2* __restrict__ pv2, int j, int lane,
                                          int sdim, int nnz, int flag, int scale, int layout) {
    int base = 0;
    int iters = (sdim + 31) >> 5;
    for (int it = 0; it < iters; it++) {
        int i = it * 32 + lane;
        bool on = false;
        if (i < sdim) {
            if (flag == 1)      on = ((const int*)mask)[(size_t)j * sdim + i] != 0;
            else if (flag == 2) on = ((const float*)mask)[(size_t)j * sdim + i] != 0.f;
            else                on = ((const unsigned char*)mask)[(size_t)j * sdim + i] != 0;
        }
        unsigned bal = __ballot_sync(0xFFFFFFFFu, on);
        if (on) {
            int k = base + __popc(bal & ((1u << lane) - 1u));
            if (k < nnz) {
                size_t slot = layout ? (2 * ((size_t)(k >> 1) * NCOLS + j) + (k & 1))
                                     : ((size_t)j * nnz + k);
                pv2[slot] = make_uint2((unsigned)(i * scale),
                                       __float_as_uint(w[(size_t)j * sdim + i]));
            }
        }
        base += __popc(bal);
    }
    if (lane == 0)
        for (int k = base; k < nnz; k++) {
            size_t slot = layout ? (2 * ((size_t)(k >> 1) * NCOLS + j) + (k & 1))
                                 : ((size_t)j * nnz + k);
            pv2[slot] = make_uint2(0u, 0u);
        }
}

#define BUILD_BLOCKS (3 * NCOLS / 8)      // 3072 (8 warps per block)
#define TRANS_BLOCKS ((ROWS * IN_DIM + 255) / 256)

__global__ void prep_all(const float* __restrict__ x, float* __restrict__ xT,
                         const void* m1, const float* __restrict__ w1,
                         const void* m2, const float* __restrict__ w2,
                         const void* m3, const float* __restrict__ w3,
                         uint2* pv1, uint2* pv2, uint2* pv3, int* nz) {
    if (blockIdx.x < BUILD_BLOCKS) {
        int warp = blockIdx.x * 8 + (threadIdx.x >> 5);
        int lane = threadIdx.x & 31;
        int layer = warp >> 13;              // NCOLS = 2^13
        int j     = warp & (NCOLS - 1);
        int f = mask_flag(m1, lane);
        if (layer == 0)      build_one(m1, w1, pv1, j, lane, IN_DIM, NNZ1P, f, XSCALE, 0);
        else if (layer == 1) build_one(m2, w2, pv2, j, lane, HID,    NNZ2,  f, 1,      1);
        else                 build_one(m3, w3, pv3, j, lane, HID,    NNZ2,  f, 1,      1);
    } else if (blockIdx.x < BUILD_BLOCKS + TRANS_BLOCKS) {
        int u = (blockIdx.x - BUILD_BLOCKS) * 256 + threadIdx.x;
        if (u >= ROWS * IN_DIM) return;
        int row = u / IN_DIM;
        int i   = u - row * IN_DIM;
        int t   = row >> 6;
        int b   = row & 63;
        xT[(size_t)(row >> 5) * (IN_DIM * TB) + i * TB + (row & 31)] =
            x[(size_t)(b * T_STEPS + t) * IN_DIM + i];
    } else {
        for (int u = threadIdx.x; u < 3 * GROUPS; u += 256) nz[u] = 0;
    }
}

// ---------------- layer-1 gemm: warp-uniform j, lane = row, ping-pong j prefetch ----------------
__global__ __launch_bounds__(256)
void gemm_float(const float* __restrict__ xT, const uint4* __restrict__ pv,
                const float* __restrict__ bias, float* __restrict__ D) {
    __shared__ float s_x[IN_DIM * XSTR];
    const int tid  = threadIdx.x;
    const int lane = tid & 31;
    const int warp = tid >> 5;
    const int g    = blockIdx.y;
    const int j0   = blockIdx.x * 512 + warp * 64;

    {
        const float* src = xT + (size_t)g * (IN_DIM * TB);
        for (int u = tid; u < IN_DIM * TB; u += 256)
            s_x[(u >> 5) * XSTR + (u & 31)] = src[u];
    }
    __syncthreads();

    const char* xbase = (const char*)s_x + lane * 4;    // idx already in byte units
    float* dlane = D + ((size_t)g * NCOLS + j0) * 32 + lane;
    const uint4* p = pv + (size_t)j0 * K2_1;            // 64*8 contiguous uint4 stream

    uint4 A[8], B[8];
#pragma unroll
    for (int k = 0; k < 8; k++) A[k] = __ldg(p + k);
    float bva = __ldg(bias + j0);

#pragma unroll 1
    for (int jj = 0; jj < 64; jj += 2) {
#pragma unroll
        for (int k = 0; k < 8; k++) B[k] = __ldg(p + (jj + 1) * 8 + k);
        float bvb = __ldg(bias + j0 + jj + 1);

        float a0 = bva, a1 = 0.f;
#pragma unroll
        for (int k = 0; k < 8; k++) {
            a0 += __uint_as_float(A[k].y) * *(const float*)(xbase + A[k].x);
            a1 += __uint_as_float(A[k].w) * *(const float*)(xbase + A[k].z);
        }
        dlane[(size_t)jj * 32] = a0 + a1;

        const int jn = (jj + 2 < 64) ? (jj + 2) : 0;
#pragma unroll
        for (int k = 0; k < 8; k++) A[k] = __ldg(p + jn * 8 + k);
        bva = __ldg(bias + j0 + jn);

        float b0 = bvb, b1 = 0.f;
#pragma unroll
        for (int k = 0; k < 8; k++) {
            b0 += __uint_as_float(B[k].y) * *(const float*)(xbase + B[k].x);
            b1 += __uint_as_float(B[k].w) * *(const float*)(xbase + B[k].z);
        }
        dlane[(size_t)(jj + 1) * 32] = b0 + b1;
    }
}

// ---------------- layer-2/3 gemm: group-skip + static 4-slot ring pipeline ----------------
#define ADDS(MASK, V)                                   \
    _Pragma("unroll")                                   \
    for (int r = 0; r < 32; r++)                        \
        if ((MASK) & (1u << r)) acc[r] += (V);

__global__ __launch_bounds__(256)
void gemm_bits(const unsigned* __restrict__ bitsIn, const uint4* __restrict__ pv,
               const float* __restrict__ bias, float* __restrict__ D,
               const int* __restrict__ nz) {
    __shared__ unsigned s_bits[HID];
    const int tid = threadIdx.x;
    const int g   = blockIdx.y;
    const int j0  = blockIdx.x * 256 + tid;

    // fast path: no spikes anywhere in this group's 32 rows -> D = bias exactly
    if (nz[g] == 0) {
        const float bv = bias[j0];
        float4 q = make_float4(bv, bv, bv, bv);
        float* dst = D + ((size_t)g * NCOLS + j0) * 32;
#pragma unroll
        for (int qq = 0; qq < 8; qq++) *(float4*)(dst + qq * 4) = q;
        return;
    }

    const unsigned* src = bitsIn + (size_t)g * HID;
    for (int u = tid; u < HID; u += 256) s_bits[u] = src[u];
    __syncthreads();

    float acc[32];
    {
        float bv = bias[j0];
#pragma unroll
        for (int r = 0; r < 32; r++) acc[r] = bv;
    }

    const uint4* base = pv + j0;
    uint4 s0 = base[(size_t)0 * NCOLS];
    uint4 s1 = base[(size_t)1 * NCOLS];
    uint4 s2 = base[(size_t)2 * NCOLS];
    uint4 s3 = base[(size_t)3 * NCOLS];
    unsigned mA0 = s_bits[s0.x], mA1 = s_bits[s0.z];
    unsigned mB0, mB1;

#pragma unroll 1
    for (int i = 0; i < K2_2; i += 4) {
        mB0 = s_bits[s1.x];  mB1 = s_bits[s1.z];
        {
            const float v0 = __uint_as_float(s0.y);
            const float v1 = __uint_as_float(s0.w);
            s0 = base[(size_t)min(i + 4, K2_2 - 1) * NCOLS];
            ADDS(mA0, v0);
            ADDS(mA1, v1);
        }
        mA0 = s_bits[s2.x];  mA1 = s_bits[s2.z];
        {
            const float v0 = __uint_as_float(s1.y);
            const float v1 = __uint_as_float(s1.w);
            s1 = base[(size_t)min(i + 5, K2_2 - 1) * NCOLS];
            ADDS(mB0, v0);
            ADDS(mB1, v1);
        }
        mB0 = s_bits[s3.x];  mB1 = s_bits[s3.z];
        {
            const float v0 = __uint_as_float(s2.y);
            const float v1 = __uint_as_float(s2.w);
            s2 = base[(size_t)min(i + 6, K2_2 - 1) * NCOLS];
            ADDS(mA0, v0);
            ADDS(mA1, v1);
        }
        mA0 = s_bits[s0.x];  mA1 = s_bits[s0.z];
        {
            const float v0 = __uint_as_float(s3.y);
            const float v1 = __uint_as_float(s3.w);
            s3 = base[(size_t)min(i + 7, K2_2 - 1) * NCOLS];
            ADDS(mB0, v0);
            ADDS(mB1, v1);
        }
    }

    float* dst = D + ((size_t)g * NCOLS + j0) * 32;
#pragma unroll
    for (int q = 0; q < 8; q++)
        *(float4*)(dst + q * 4) = make_float4(acc[q*4], acc[q*4+1], acc[q*4+2], acc[q*4+3]);
}

// ---------------- scan producing spike BITMASKS + any-spike flags ----------------
// Warp = fixed h, 32 consecutive b. 150 = 6 x 25. Flags: benign racy store of 1.
__global__ __launch_bounds__(128)
void scan_bits(const float* __restrict__ D, const float* __restrict__ tau_m,
               const float* __restrict__ tau_n, unsigned* __restrict__ bitsOut,
               int* __restrict__ nz) {
    int tid  = blockIdx.x * 128 + threadIdx.x;      // 0 .. 65535
    int h    = tid >> 6;
    int b    = tid & 63;
    int hi   = b >> 5;                               // warp-uniform
    int lane = threadIdx.x & 31;                     // == b & 31

    float beta[8], omb[8];
#pragma unroll
    for (int n = 0; n < 8; n++) {
        float bb = 1.f / (1.f + expf(-tau_n[h * 8 + n]));
        beta[n] = bb; omb[n] = 1.f - bb;
    }
    float alpha = 1.f / (1.f + expf(-tau_m[h]));
    float oma   = 1.f - alpha;

    float d[8];
#pragma unroll
    for (int n = 0; n < 8; n++) d[n] = 0.f;
    float mem = 0.f, spk = 0.f;

    const size_t tstride = (size_t)2 * NCOLS * 32;   // per-t stride in floats
    const float* dbase = D + ((size_t)hi * NCOLS + h * 8) * 32 + lane;

    float S[6][8];
#pragma unroll
    for (int s = 0; s < 6; s++) {
        const float* p = dbase + (size_t)s * tstride;
#pragma unroll
        for (int n = 0; n < 8; n++) S[s][n] = p[n * 32];
    }

#pragma unroll 1
    for (int i = 0; i < 25; i++) {
        const int t0 = i * 6;
#pragma unroll
        for (int s = 0; s < 6; s++) {
            const int t = t0 + s;
#pragma unroll
            for (int n = 0; n < 8; n++)
                d[n] = beta[n] * d[n] + omb[n] * S[s][n];
            {
                const int tp = (t + 6 < T_STEPS) ? (t + 6) : t;
                const float* p = dbase + (size_t)tp * tstride;
#pragma unroll
                for (int n = 0; n < 8; n++) S[s][n] = p[n * 32];
            }
            float l = ((d[0] + d[1]) + (d[2] + d[3])) + ((d[4] + d[5]) + (d[6] + d[7]));
            mem = mem * alpha + oma * l - spk;
            bool fired = mem > 1.0f;
            spk = fired ? 1.0f : 0.0f;
            unsigned bal = __ballot_sync(0xFFFFFFFFu, fired);
            if (lane == 0) {
                int grp = t * 2 + hi;
                bitsOut[(size_t)grp * HID + h] = bal;
                if (bal) nz[grp] = 1;                // any-spike flag (racy-benign)
            }
        }
    }
}

// ---------------- readout from spike bitmasks (group-skip aware) ----------------
#define RO_THREADS 280          // 35 o x 8 chunks
__global__ __launch_bounds__(RO_THREADS)
void readout_bits(const unsigned* __restrict__ bitsIn, const float* __restrict__ wr,
                  const float* __restrict__ br, float* __restrict__ rOut,
                  const int* __restrict__ nz) {
    __shared__ unsigned s_bits[HID];
    __shared__ float    s_red[RO_THREADS * 32];
    const int tid = threadIdx.x;
    const int g   = blockIdx.x;

    if (nz[g] == 0) {                        // no spikes in this group -> r = br exactly
        for (int u = tid; u < OUT_DIM * 32; u += RO_THREADS) {
            int oo  = u >> 5;
            int row = u & 31;
            rOut[(size_t)(g * TB + row) * OUT_DIM + oo] = br[oo];
        }
        return;
    }

    const unsigned* src = bitsIn + (size_t)g * HID;
    for (int u = tid; u < HID; u += RO_THREADS) s_bits[u] = src[u];
    __syncthreads();

    const int o     = tid >> 3;          // 0..34
    const int chunk = tid & 7;           // 0..7
    float acc[32];
#pragma unroll
    for (int r = 0; r < 32; r++) acc[r] = 0.f;

    const float* wrow = wr + o * HID + chunk * 128;
    const unsigned* mb = s_bits + chunk * 128;
#pragma unroll 4
    for (int i = 0; i < 128; i++) {
        unsigned m = mb[i];
        float    v = wrow[i];
#pragma unroll
        for (int r = 0; r < 32; r++)
            if (m & (1u << r)) acc[r] += v;
    }
#pragma unroll
    for (int r = 0; r < 32; r++) s_red[tid * 32 + r] = acc[r];
    __syncthreads();

    for (int u = tid; u < OUT_DIM * 32; u += RO_THREADS) {
        int oo  = u >> 5;
        int row = u & 31;
        float s = br[oo];
#pragma unroll
        for (int c = 0; c < 8; c++)
            s += s_red[(oo * 8 + c) * 32 + row];
        rOut[(size_t)(g * TB + row) * OUT_DIM + oo] = s;
    }
}

// ---------------- readout leaky scan + mean + log_softmax ----------------
__global__ void final_k(const float* __restrict__ rIn, const float* __restrict__ tau_mr,
                        float* __restrict__ out) {
    int b = blockIdx.x;
    int o = threadIdx.x;                     // blockDim = 64, only o<35 active
    __shared__ float sv[64];
    __shared__ float s_mx, s_ls;
    float acc = 0.f;
    if (o < OUT_DIM) {
        float alpha = 1.f / (1.f + expf(-tau_mr[o]));
        float oma = 1.f - alpha;
        float mr = 0.f;
        for (int t = 0; t < T_STEPS; t++) {
            mr = mr * alpha + oma * rIn[(size_t)(t * 64 + b) * OUT_DIM + o];
            acc += mr;
        }
        acc /= (float)T_STEPS;
    }
    sv[o] = (o < OUT_DIM) ? acc : -1e30f;
    __syncthreads();
    if (o == 0) {
        float m = -1e30f;
        for (int i = 0; i < OUT_DIM; i++) m = fmaxf(m, sv[i]);
        float s = 0.f;
        for (int i = 0; i < OUT_DIM; i++) s += expf(sv[i] - m);
        s_mx = m; s_ls = logf(s);
    }
    __syncthreads();
    if (o < OUT_DIM) out[b * OUT_DIM + o] = sv[o] - s_mx - s_ls;
}

// ---------------- launch ----------------
extern "C" void kernel_launch(void* const* d_in, const int* in_sizes, int n_in,
                              void* d_out, int out_size) {
    (void)in_sizes; (void)n_in; (void)out_size;
    const float* x   = (const float*)d_in[0];
    const float* w1  = (const float*)d_in[1];
    const float* b1  = (const float*)d_in[2];
    const float* tm1 = (const float*)d_in[3];
    const float* tn1 = (const float*)d_in[4];
    const float* w2  = (const float*)d_in[5];
    const float* b2  = (const float*)d_in[6];
    const float* tm2 = (const float*)d_in[7];
    const float* tn2 = (const float*)d_in[8];
    const float* w3  = (const float*)d_in[9];
    const float* b3  = (const float*)d_in[10];
    const float* tm3 = (const float*)d_in[11];
    const float* tn3 = (const float*)d_in[12];
    const float* wr  = (const float*)d_in[13];
    const float* br  = (const float*)d_in[14];
    const float* tmr = (const float*)d_in[15];
    const void*  m1  = d_in[16];
    const void*  m2  = d_in[17];
    const void*  m3  = d_in[18];
    float* out = (float*)d_out;

    void *pD, *pB, *pxT, *pr, *pv1, *pv2, *pv3, *pnz;
    cudaGetSymbolAddress(&pD,  g_D);
    cudaGetSymbolAddress(&pB,  g_bits);
    cudaGetSymbolAddress(&pxT, g_xT);
    cudaGetSymbolAddress(&pr,  g_r);
    cudaGetSymbolAddress(&pv1, g_pv1);
    cudaGetSymbolAddress(&pv2, g_pv2);
    cudaGetSymbolAddress(&pv3, g_pv3);
    cudaGetSymbolAddress(&pnz, g_nz);

    int* nz = (int*)pnz;

    // 1) merged prep: dtype detect + CSR build + x transpose + flag zeroing
    prep_all<<<BUILD_BLOCKS + TRANS_BLOCKS + 1, 256>>>(
        x, (float*)pxT, m1, w1, m2, w2, m3, w3,
        (uint2*)pv1, (uint2*)pv2, (uint2*)pv3, nz);

    dim3 gf(NCOLS / 512, GROUPS);
    dim3 gb(NCOLS / 256, GROUPS);
    const int scan_blocks = (BSZ * HID) / 128;

    // 2) layer 1 (float input) -> spike bitmasks + flags[0]
    gemm_float<<<gf, 256>>>((const float*)pxT, (const uint4*)pv1, b1, (float*)pD);
    scan_bits<<<scan_blocks, 128>>>((const float*)pD, tm1, tn1, (unsigned*)pB, nz + 0 * GROUPS);

    // 3) layer 2 (bitmask input, skip zero groups) -> spike bitmasks + flags[1]
    gemm_bits<<<gb, 256>>>((const unsigned*)pB, (const uint4*)pv2, b2, (float*)pD, nz + 0 * GROUPS);
    scan_bits<<<scan_blocks, 128>>>((const float*)pD, tm2, tn2, (unsigned*)pB, nz + 1 * GROUPS);

    // 4) layer 3 (bitmask input, skip zero groups) -> spike bitmasks + flags[2]
    gemm_bits<<<gb, 256>>>((const unsigned*)pB, (const uint4*)pv3, b3, (float*)pD, nz + 1 * GROUPS);
    scan_bits<<<scan_blocks, 128>>>((const float*)pD, tm3, tn3, (unsigned*)pB, nz + 2 * GROUPS);

    // 5) readout from bits (skip zero groups) + final scan + log_softmax
    readout_bits<<<GROUPS, RO_THREADS>>>((const unsigned*)pB, wr, br, (float*)pr, nz + 2 * GROUPS);
    final_k<<<BSZ, 64>>>((const float*)pr, tmr, out);
}

// round 16
// speedup vs baseline: 3.0470x; 1.3276x over previous
#include <cuda_runtime.h>
#include <math.h>
#include <stdint.h>

// ---------------- problem constants ----------------
#define BSZ      64
#define T_STEPS  150
#define IN_DIM   120
#define HID      1024
#define OUT_DIM  35
#define NB       8
#define NCOLS    8192          // HID*NB
#define ROWS     9600          // T_STEPS*BSZ
#define TB       32            // (t,b) rows per gemm group (= one ballot word)
#define GROUPS   300           // ROWS/TB
#define NNZ1P    16            // IN_DIM/NB = 15, padded to 16 (pad: idx=0,val=0 -> exact no-op)
#define NNZ2     128           // HID/NB
#define K2_1     8             // NNZ1P/2
#define K2_2     64            // NNZ2/2
#define XSTR     33            // s_x row stride in floats (conflict-free)
#define XSCALE   (XSTR * 4)    // idx prescale for layer 1: byte offset of row idx

// D layout: [group][j][32 rows]
__device__ float    g_D   [(size_t)ROWS * NCOLS];
__device__ unsigned g_bits[(size_t)GROUPS * HID];        // spike bitmasks: [group][i], bit r = row r
__device__ float    g_xT  [(size_t)GROUPS * IN_DIM * TB];
__device__ float    g_r   [(size_t)ROWS * OUT_DIM];
__device__ uint4    g_pv1 [NCOLS * K2_1];                // layer 1: [j][k2], idx prescaled to BYTE offsets
__device__ uint4    g_pv2 [K2_2 * NCOLS];                // layers 2/3: [k2][j]
__device__ uint4    g_pv3 [K2_2 * NCOLS];
__device__ int      g_nz  [3 * GROUPS];                  // per-(layer,group) any-spike flags

// ---------------- merged prep: mask-dtype detect + CSR build + x transpose + flag zero ----------------
__device__ __forceinline__ int mask_flag(const void* m1, int lane) {
    int  si = 0;   bool oki = true;
    float sf = 0.f; bool okf = true;
#pragma unroll
    for (int it = 0; it < 4; it++) {
        int i = it * 32 + lane;
        if (i < IN_DIM) {
            int v = ((const int*)m1)[i];
            if (v != 0 && v != 1) oki = false;
            si += v;
            float f = ((const float*)m1)[i];
            if (f != 0.f && f != 1.f) okf = false;
            sf += f;
        }
    }
#pragma unroll
    for (int s = 16; s > 0; s >>= 1) {
        si += __shfl_xor_sync(0xFFFFFFFFu, si, s);
        sf += __shfl_xor_sync(0xFFFFFFFFu, sf, s);
    }
    oki = __all_sync(0xFFFFFFFFu, oki);
    okf = __all_sync(0xFFFFFFFFu, okf);
    if (oki && si == 15) return 1;
    if (okf && sf == 15.0f) return 2;
    return 0;
}

__device__ __forceinline__ void build_one(const void* mask, const float* __restrict__ w,
                                          uint2* __restrict__ pv2, int j, int lane,
                                          int sdim, int nnz, int flag, int scale, int layout) {
    int base = 0;
    int iters = (sdim + 31) >> 5;
    for (int it = 0; it < iters; it++) {
        int i = it * 32 + lane;
        bool on = false;
        if (i < sdim) {
            if (flag == 1)      on = ((const int*)mask)[(size_t)j * sdim + i] != 0;
            else if (flag == 2) on = ((const float*)mask)[(size_t)j * sdim + i] != 0.f;
            else                on = ((const unsigned char*)mask)[(size_t)j * sdim + i] != 0;
        }
        unsigned bal = __ballot_sync(0xFFFFFFFFu, on);
        if (on) {
            int k = base + __popc(bal & ((1u << lane) - 1u));
            if (k < nnz) {
                size_t slot = layout ? (2 * ((size_t)(k >> 1) * NCOLS + j) + (k & 1))
                                     : ((size_t)j * nnz + k);
                pv2[slot] = make_uint2((unsigned)(i * scale),
                                       __float_as_uint(w[(size_t)j * sdim + i]));
            }
        }
        base += __popc(bal);
    }
    if (lane == 0)
        for (int k = base; k < nnz; k++) {
            size_t slot = layout ? (2 * ((size_t)(k >> 1) * NCOLS + j) + (k & 1))
                                 : ((size_t)j * nnz + k);
            pv2[slot] = make_uint2(0u, 0u);
        }
}

#define BUILD_BLOCKS (3 * NCOLS / 8)      // 3072 (8 warps per block)
#define TRANS_BLOCKS ((ROWS * IN_DIM + 255) / 256)

__global__ void prep_all(const float* __restrict__ x, float* __restrict__ xT,
                         const void* m1, const float* __restrict__ w1,
                         const void* m2, const float* __restrict__ w2,
                         const void* m3, const float* __restrict__ w3,
                         uint2* pv1, uint2* pv2, uint2* pv3, int* nz) {
    if (blockIdx.x < BUILD_BLOCKS) {
        int warp = blockIdx.x * 8 + (threadIdx.x >> 5);
        int lane = threadIdx.x & 31;
        int layer = warp >> 13;              // NCOLS = 2^13
        int j     = warp & (NCOLS - 1);
        int f = mask_flag(m1, lane);
        if (layer == 0)      build_one(m1, w1, pv1, j, lane, IN_DIM, NNZ1P, f, XSCALE, 0);
        else if (layer == 1) build_one(m2, w2, pv2, j, lane, HID,    NNZ2,  f, 1,      1);
        else                 build_one(m3, w3, pv3, j, lane, HID,    NNZ2,  f, 1,      1);
    } else if (blockIdx.x < BUILD_BLOCKS + TRANS_BLOCKS) {
        int u = (blockIdx.x - BUILD_BLOCKS) * 256 + threadIdx.x;
        if (u >= ROWS * IN_DIM) return;
        int row = u / IN_DIM;
        int i   = u - row * IN_DIM;
        int t   = row >> 6;
        int b   = row & 63;
        xT[(size_t)(row >> 5) * (IN_DIM * TB) + i * TB + (row & 31)] =
            x[(size_t)(b * T_STEPS + t) * IN_DIM + i];
    } else {
        for (int u = threadIdx.x; u < 3 * GROUPS; u += 256) nz[u] = 0;
    }
}

// ---------------- layer-1 gemm: warp-uniform j, lane = row, ping-pong j prefetch ----------------
__global__ __launch_bounds__(256)
void gemm_float(const float* __restrict__ xT, const uint4* __restrict__ pv,
                const float* __restrict__ bias, float* __restrict__ D) {
    __shared__ float s_x[IN_DIM * XSTR];
    const int tid  = threadIdx.x;
    const int lane = tid & 31;
    const int warp = tid >> 5;
    const int g    = blockIdx.y;
    const int j0   = blockIdx.x * 512 + warp * 64;

    {
        const float* src = xT + (size_t)g * (IN_DIM * TB);
        for (int u = tid; u < IN_DIM * TB; u += 256)
            s_x[(u >> 5) * XSTR + (u & 31)] = src[u];
    }
    __syncthreads();

    const char* xbase = (const char*)s_x + lane * 4;    // idx already in byte units
    float* dlane = D + ((size_t)g * NCOLS + j0) * 32 + lane;
    const uint4* p = pv + (size_t)j0 * K2_1;            // 64*8 contiguous uint4 stream

    uint4 A[8], B[8];
#pragma unroll
    for (int k = 0; k < 8; k++) A[k] = __ldg(p + k);
    float bva = __ldg(bias + j0);

#pragma unroll 1
    for (int jj = 0; jj < 64; jj += 2) {
#pragma unroll
        for (int k = 0; k < 8; k++) B[k] = __ldg(p + (jj + 1) * 8 + k);
        float bvb = __ldg(bias + j0 + jj + 1);

        float a0 = bva, a1 = 0.f;
#pragma unroll
        for (int k = 0; k < 8; k++) {
            a0 += __uint_as_float(A[k].y) * *(const float*)(xbase + A[k].x);
            a1 += __uint_as_float(A[k].w) * *(const float*)(xbase + A[k].z);
        }
        dlane[(size_t)jj * 32] = a0 + a1;

        const int jn = (jj + 2 < 64) ? (jj + 2) : 0;
#pragma unroll
        for (int k = 0; k < 8; k++) A[k] = __ldg(p + jn * 8 + k);
        bva = __ldg(bias + j0 + jn);

        float b0 = bvb, b1 = 0.f;
#pragma unroll
        for (int k = 0; k < 8; k++) {
            b0 += __uint_as_float(B[k].y) * *(const float*)(xbase + B[k].x);
            b1 += __uint_as_float(B[k].w) * *(const float*)(xbase + B[k].z);
        }
        dlane[(size_t)(jj + 1) * 32] = b0 + b1;
    }
}

// ---------------- layer-2/3 gemm: zero-flag groups do NOTHING (scan substitutes bias) ----------------
#define ADDS(MASK, V)                                   \
    _Pragma("unroll")                                   \
    for (int r = 0; r < 32; r++)                        \
        if ((MASK) & (1u << r)) acc[r] += (V);

__global__ __launch_bounds__(256)
void gemm_bits(const unsigned* __restrict__ bitsIn, const uint4* __restrict__ pv,
               const float* __restrict__ bias, float* __restrict__ D,
               const int* __restrict__ nz) {
    const int g = blockIdx.y;
    if (nz[g] == 0) return;                  // scan_sparse substitutes bias exactly

    __shared__ unsigned s_bits[HID];
    const int tid = threadIdx.x;
    const int j0  = blockIdx.x * 256 + tid;

    const unsigned* src = bitsIn + (size_t)g * HID;
    for (int u = tid; u < HID; u += 256) s_bits[u] = src[u];
    __syncthreads();

    float acc[32];
    {
        float bv = bias[j0];
#pragma unroll
        for (int r = 0; r < 32; r++) acc[r] = bv;
    }

    const uint4* base = pv + j0;
    uint4 s0 = base[(size_t)0 * NCOLS];
    uint4 s1 = base[(size_t)1 * NCOLS];
    uint4 s2 = base[(size_t)2 * NCOLS];
    uint4 s3 = base[(size_t)3 * NCOLS];
    unsigned mA0 = s_bits[s0.x], mA1 = s_bits[s0.z];
    unsigned mB0, mB1;

#pragma unroll 1
    for (int i = 0; i < K2_2; i += 4) {
        mB0 = s_bits[s1.x];  mB1 = s_bits[s1.z];
        {
            const float v0 = __uint_as_float(s0.y);
            const float v1 = __uint_as_float(s0.w);
            s0 = base[(size_t)min(i + 4, K2_2 - 1) * NCOLS];
            ADDS(mA0, v0);
            ADDS(mA1, v1);
        }
        mA0 = s_bits[s2.x];  mA1 = s_bits[s2.z];
        {
            const float v0 = __uint_as_float(s1.y);
            const float v1 = __uint_as_float(s1.w);
            s1 = base[(size_t)min(i + 5, K2_2 - 1) * NCOLS];
            ADDS(mB0, v0);
            ADDS(mB1, v1);
        }
        mB0 = s_bits[s3.x];  mB1 = s_bits[s3.z];
        {
            const float v0 = __uint_as_float(s2.y);
            const float v1 = __uint_as_float(s2.w);
            s2 = base[(size_t)min(i + 6, K2_2 - 1) * NCOLS];
            ADDS(mA0, v0);
            ADDS(mA1, v1);
        }
        mA0 = s_bits[s0.x];  mA1 = s_bits[s0.z];
        {
            const float v0 = __uint_as_float(s3.y);
            const float v1 = __uint_as_float(s3.w);
            s3 = base[(size_t)min(i + 7, K2_2 - 1) * NCOLS];
            ADDS(mB0, v0);
            ADDS(mB1, v1);
        }
    }

    float* dst = D + ((size_t)g * NCOLS + j0) * 32;
#pragma unroll
    for (int q = 0; q < 8; q++)
        *(float4*)(dst + q * 4) = make_float4(acc[q*4], acc[q*4+1], acc[q*4+2], acc[q*4+3]);
}

// ---------------- layer-1 scan: dense D stream, 6-slot prefetch ----------------
__global__ __launch_bounds__(128)
void scan_bits(const float* __restrict__ D, const float* __restrict__ tau_m,
               const float* __restrict__ tau_n, unsigned* __restrict__ bitsOut,
               int* __restrict__ nz) {
    int tid  = blockIdx.x * 128 + threadIdx.x;
    int h    = tid >> 6;
    int b    = tid & 63;
    int hi   = b >> 5;
    int lane = threadIdx.x & 31;

    float beta[8], omb[8];
#pragma unroll
    for (int n = 0; n < 8; n++) {
        float bb = 1.f / (1.f + expf(-tau_n[h * 8 + n]));
        beta[n] = bb; omb[n] = 1.f - bb;
    }
    float alpha = 1.f / (1.f + expf(-tau_m[h]));
    float oma   = 1.f - alpha;

    float d[8];
#pragma unroll
    for (int n = 0; n < 8; n++) d[n] = 0.f;
    float mem = 0.f, spk = 0.f;

    const size_t tstride = (size_t)2 * NCOLS * 32;
    const float* dbase = D + ((size_t)hi * NCOLS + h * 8) * 32 + lane;

    float S[6][8];
#pragma unroll
    for (int s = 0; s < 6; s++) {
        const float* p = dbase + (size_t)s * tstride;
#pragma unroll
        for (int n = 0; n < 8; n++) S[s][n] = p[n * 32];
    }

#pragma unroll 1
    for (int i = 0; i < 25; i++) {
        const int t0 = i * 6;
#pragma unroll
        for (int s = 0; s < 6; s++) {
            const int t = t0 + s;
#pragma unroll
            for (int n = 0; n < 8; n++)
                d[n] = beta[n] * d[n] + omb[n] * S[s][n];
            {
                const int tp = (t + 6 < T_STEPS) ? (t + 6) : t;
                const float* p = dbase + (size_t)tp * tstride;
#pragma unroll
                for (int n = 0; n < 8; n++) S[s][n] = p[n * 32];
            }
            float l = ((d[0] + d[1]) + (d[2] + d[3])) + ((d[4] + d[5]) + (d[6] + d[7]));
            mem = mem * alpha + oma * l - spk;
            bool fired = mem > 1.0f;
            spk = fired ? 1.0f : 0.0f;
            unsigned bal = __ballot_sync(0xFFFFFFFFu, fired);
            if (lane == 0) {
                int grp = t * 2 + hi;
                bitsOut[(size_t)grp * HID + h] = bal;
                if (bal) nz[grp] = 1;
            }
        }
    }
}

// ---------------- layer-2/3 scan: flag-aware (bias substitution; D read only if spikes) ----------------
__global__ __launch_bounds__(128)
void scan_sparse(const float* __restrict__ D, const float* __restrict__ bias,
                 const float* __restrict__ tau_m, const float* __restrict__ tau_n,
                 unsigned* __restrict__ bitsOut,
                 const int* __restrict__ nzIn, int* __restrict__ nzOut) {
    int tid  = blockIdx.x * 128 + threadIdx.x;
    int h    = tid >> 6;
    int b    = tid & 63;
    int hi   = b >> 5;
    int lane = threadIdx.x & 31;

    float beta[8], omb[8], bv[8];
#pragma unroll
    for (int n = 0; n < 8; n++) {
        float bb = 1.f / (1.f + expf(-tau_n[h * 8 + n]));
        beta[n] = bb; omb[n] = 1.f - bb;
        bv[n] = bias[h * 8 + n];
    }
    float alpha = 1.f / (1.f + expf(-tau_m[h]));
    float oma   = 1.f - alpha;

    float d[8];
#pragma unroll
    for (int n = 0; n < 8; n++) d[n] = 0.f;
    float mem = 0.f, spk = 0.f;

    const size_t tstride = (size_t)2 * NCOLS * 32;
    const float* dbase = D + ((size_t)hi * NCOLS + h * 8) * 32 + lane;

    int flag_next = nzIn[hi];                        // flag for t = 0

#pragma unroll 1
    for (int t = 0; t < T_STEPS; t++) {
        int flag = flag_next;
        if (t + 1 < T_STEPS) flag_next = nzIn[(t + 1) * 2 + hi];

        float q[8];
        if (flag) {                                  // warp-uniform branch (rare)
            const float* p = dbase + (size_t)t * tstride;
#pragma unroll
            for (int n = 0; n < 8; n++) q[n] = p[n * 32];
        } else {
#pragma unroll
            for (int n = 0; n < 8; n++) q[n] = bv[n];
        }
#pragma unroll
        for (int n = 0; n < 8; n++)
            d[n] = beta[n] * d[n] + omb[n] * q[n];
        float l = ((d[0] + d[1]) + (d[2] + d[3])) + ((d[4] + d[5]) + (d[6] + d[7]));
        mem = mem * alpha + oma * l - spk;
        bool fired = mem > 1.0f;
        spk = fired ? 1.0f : 0.0f;
        unsigned bal = __ballot_sync(0xFFFFFFFFu, fired);
        if (lane == 0) {
            int grp = t * 2 + hi;
            bitsOut[(size_t)grp * HID + h] = bal;
            if (bal) nzOut[grp] = 1;
        }
    }
}

// ---------------- readout from spike bitmasks (group-skip aware) ----------------
#define RO_THREADS 280          // 35 o x 8 chunks
__global__ __launch_bounds__(RO_THREADS)
void readout_bits(const unsigned* __restrict__ bitsIn, const float* __restrict__ wr,
                  const float* __restrict__ br, float* __restrict__ rOut,
                  const int* __restrict__ nz) {
    __shared__ unsigned s_bits[HID];
    __shared__ float    s_red[RO_THREADS * 32];
    const int tid = threadIdx.x;
    const int g   = blockIdx.x;

    if (nz[g] == 0) {
        for (int u = tid; u < OUT_DIM * 32; u += RO_THREADS) {
            int oo  = u >> 5;
            int row = u & 31;
            rOut[(size_t)(g * TB + row) * OUT_DIM + oo] = br[oo];
        }
        return;
    }

    const unsigned* src = bitsIn + (size_t)g * HID;
    for (int u = tid; u < HID; u += RO_THREADS) s_bits[u] = src[u];
    __syncthreads();

    const int o     = tid >> 3;
    const int chunk = tid & 7;
    float acc[32];
#pragma unroll
    for (int r = 0; r < 32; r++) acc[r] = 0.f;

    const float* wrow = wr + o * HID + chunk * 128;
    const unsigned* mb = s_bits + chunk * 128;
#pragma unroll 4
    for (int i = 0; i < 128; i++) {
        unsigned m = mb[i];
        float    v = wrow[i];
#pragma unroll
        for (int r = 0; r < 32; r++)
            if (m & (1u << r)) acc[r] += v;
    }
#pragma unroll
    for (int r = 0; r < 32; r++) s_red[tid * 32 + r] = acc[r];
    __syncthreads();

    for (int u = tid; u < OUT_DIM * 32; u += RO_THREADS) {
        int oo  = u >> 5;
        int row = u & 31;
        float s = br[oo];
#pragma unroll
        for (int c = 0; c < 8; c++)
            s += s_red[(oo * 8 + c) * 32 + row];
        rOut[(size_t)(g * TB + row) * OUT_DIM + oo] = s;
    }
}

// ---------------- readout leaky scan + mean + log_softmax ----------------
__global__ void final_k(const float* __restrict__ rIn, const float* __restrict__ tau_mr,
                        float* __restrict__ out) {
    int b = blockIdx.x;
    int o = threadIdx.x;                     // blockDim = 64, only o<35 active
    __shared__ float sv[64];
    __shared__ float s_mx, s_ls;
    float acc = 0.f;
    if (o < OUT_DIM) {
        float alpha = 1.f / (1.f + expf(-tau_mr[o]));
        float oma = 1.f - alpha;
        float mr = 0.f;
        for (int t = 0; t < T_STEPS; t++) {
            mr = mr * alpha + oma * rIn[(size_t)(t * 64 + b) * OUT_DIM + o];
            acc += mr;
        }
        acc /= (float)T_STEPS;
    }
    sv[o] = (o < OUT_DIM) ? acc : -1e30f;
    __syncthreads();
    if (o == 0) {
        float m = -1e30f;
        for (int i = 0; i < OUT_DIM; i++) m = fmaxf(m, sv[i]);
        float s = 0.f;
        for (int i = 0; i < OUT_DIM; i++) s += expf(sv[i] - m);
        s_mx = m; s_ls = logf(s);
    }
    __syncthreads();
    if (o < OUT_DIM) out[b * OUT_DIM + o] = sv[o] - s_mx - s_ls;
}

// ---------------- launch ----------------
extern "C" void kernel_launch(void* const* d_in, const int* in_sizes, int n_in,
                              void* d_out, int out_size) {
    (void)in_sizes; (void)n_in; (void)out_size;
    const float* x   = (const float*)d_in[0];
    const float* w1  = (const float*)d_in[1];
    const float* b1  = (const float*)d_in[2];
    const float* tm1 = (const float*)d_in[3];
    const float* tn1 = (const float*)d_in[4];
    const float* w2  = (const float*)d_in[5];
    const float* b2  = (const float*)d_in[6];
    const float* tm2 = (const float*)d_in[7];
    const float* tn2 = (const float*)d_in[8];
    const float* w3  = (const float*)d_in[9];
    const float* b3  = (const float*)d_in[10];
    const float* tm3 = (const float*)d_in[11];
    const float* tn3 = (const float*)d_in[12];
    const float* wr  = (const float*)d_in[13];
    const float* br  = (const float*)d_in[14];
    const float* tmr = (const float*)d_in[15];
    const void*  m1  = d_in[16];
    const void*  m2  = d_in[17];
    const void*  m3  = d_in[18];
    float* out = (float*)d_out;

    void *pD, *pB, *pxT, *pr, *pv1, *pv2, *pv3, *pnz;
    cudaGetSymbolAddress(&pD,  g_D);
    cudaGetSymbolAddress(&pB,  g_bits);
    cudaGetSymbolAddress(&pxT, g_xT);
    cudaGetSymbolAddress(&pr,  g_r);
    cudaGetSymbolAddress(&pv1, g_pv1);
    cudaGetSymbolAddress(&pv2, g_pv2);
    cudaGetSymbolAddress(&pv3, g_pv3);
    cudaGetSymbolAddress(&pnz, g_nz);

    int* nz = (int*)pnz;

    // 1) merged prep
    prep_all<<<BUILD_BLOCKS + TRANS_BLOCKS + 1, 256>>>(
        x, (float*)pxT, m1, w1, m2, w2, m3, w3,
        (uint2*)pv1, (uint2*)pv2, (uint2*)pv3, nz);

    dim3 gf(NCOLS / 512, GROUPS);
    dim3 gb(NCOLS / 256, GROUPS);
    const int scan_blocks = (BSZ * HID) / 128;

    // 2) layer 1 (dense): gemm -> D; dense scan -> bits + flags[0]
    gemm_float<<<gf, 256>>>((const float*)pxT, (const uint4*)pv1, b1, (float*)pD);
    scan_bits<<<scan_blocks, 128>>>((const float*)pD, tm1, tn1, (unsigned*)pB, nz + 0 * GROUPS);

    // 3) layer 2: gemm only for spiking groups; flag-aware scan (bias substitution)
    gemm_bits<<<gb, 256>>>((const unsigned*)pB, (const uint4*)pv2, b2, (float*)pD, nz + 0 * GROUPS);
    scan_sparse<<<scan_blocks, 128>>>((const float*)pD, b2, tm2, tn2, (unsigned*)pB,
                                      nz + 0 * GROUPS, nz + 1 * GROUPS);

    // 4) layer 3: same
    gemm_bits<<<gb, 256>>>((const unsigned*)pB, (const uint4*)pv3, b3, (float*)pD, nz + 1 * GROUPS);
    scan_sparse<<<scan_blocks, 128>>>((const float*)pD, b3, tm3, tn3, (unsigned*)pB,
                                      nz + 1 * GROUPS, nz + 2 * GROUPS);

    // 5) readout from bits (skip zero groups) + final scan + log_softmax
    readout_bits<<<GROUPS, RO_THREADS>>>((const unsigned*)pB, wr, br, (float*)pr, nz + 2 * GROUPS);
    final_k<<<BSZ, 64>>>((const float*)pr, tmr, out);
}

// round 17
// speedup vs baseline: 3.0988x; 1.0170x over previous
#include <cuda_runtime.h>
#include <math.h>
#include <stdint.h>

// ---------------- problem constants ----------------
#define BSZ      64
#define T_STEPS  150
#define IN_DIM   120
#define HID      1024
#define OUT_DIM  35
#define NB       8
#define NCOLS    8192          // HID*NB
#define ROWS     9600          // T_STEPS*BSZ
#define TB       32            // (t,b) rows per group (= one ballot word)
#define GROUPS   300           // ROWS/TB
#define NNZ1P    16            // IN_DIM/NB = 15, padded to 16 (pad: idx=0,val=0 -> exact no-op)
#define NNZ2     128           // HID/NB
#define K2_1     8             // NNZ1P/2
#define K2_2     64            // NNZ2/2
#define X2STR    36            // fused-kernel s_x row stride (words); 144B, float4-aligned, conflict-free
#define XSCALE   (X2STR * 4)   // layer-1 idx prescale: byte offset of row idx in s_x

// D layout: [group][j][32 rows] (only layers 2/3 spiking groups use it now)
__device__ float    g_D   [(size_t)ROWS * NCOLS];
__device__ unsigned g_bits[(size_t)GROUPS * HID];        // spike bitmasks: [group][i], bit r = row r
__device__ float    g_xT  [(size_t)GROUPS * IN_DIM * TB];
__device__ float    g_r   [(size_t)ROWS * OUT_DIM];
__device__ uint4    g_pv1 [NCOLS * K2_1];                // layer 1: [j][k2], idx prescaled to BYTE offsets
__device__ uint4    g_pv2 [K2_2 * NCOLS];                // layers 2/3: [k2][j]
__device__ uint4    g_pv3 [K2_2 * NCOLS];
__device__ int      g_nz  [3 * GROUPS];                  // per-(layer,group) any-spike flags

// ---------------- merged prep: mask-dtype detect + CSR build + x transpose + flag zero ----------------
__device__ __forceinline__ int mask_flag(const void* m1, int lane) {
    int  si = 0;   bool oki = true;
    float sf = 0.f; bool okf = true;
#pragma unroll
    for (int it = 0; it < 4; it++) {
        int i = it * 32 + lane;
        if (i < IN_DIM) {
            int v = ((const int*)m1)[i];
            if (v != 0 && v != 1) oki = false;
            si += v;
            float f = ((const float*)m1)[i];
            if (f != 0.f && f != 1.f) okf = false;
            sf += f;
        }
    }
#pragma unroll
    for (int s = 16; s > 0; s >>= 1) {
        si += __shfl_xor_sync(0xFFFFFFFFu, si, s);
        sf += __shfl_xor_sync(0xFFFFFFFFu, sf, s);
    }
    oki = __all_sync(0xFFFFFFFFu, oki);
    okf = __all_sync(0xFFFFFFFFu, okf);
    if (oki && si == 15) return 1;
    if (okf && sf == 15.0f) return 2;
    return 0;
}

__device__ __forceinline__ void build_one(const void* mask, const float* __restrict__ w,
                                          uint2* __restrict__ pv2, int j, int lane,
                                          int sdim, int nnz, int flag, int scale, int layout) {
    int base = 0;
    int iters = (sdim + 31) >> 5;
    for (int it = 0; it < iters; it++) {
        int i = it * 32 + lane;
        bool on = false;
        if (i < sdim) {
            if (flag == 1)      on = ((const int*)mask)[(size_t)j * sdim + i] != 0;
            else if (flag == 2) on = ((const float*)mask)[(size_t)j * sdim + i] != 0.f;
            else                on = ((const unsigned char*)mask)[(size_t)j * sdim + i] != 0;
        }
        unsigned bal = __ballot_sync(0xFFFFFFFFu, on);
        if (on) {
            int k = base + __popc(bal & ((1u << lane) - 1u));
            if (k < nnz) {
                size_t slot = layout ? (2 * ((size_t)(k >> 1) * NCOLS + j) + (k & 1))
                                     : ((size_t)j * nnz + k);
                pv2[slot] = make_uint2((unsigned)(i * scale),
                                       __float_as_uint(w[(size_t)j * sdim + i]));
            }
        }
        base += __popc(bal);
    }
    if (lane == 0)
        for (int k = base; k < nnz; k++) {
            size_t slot = layout ? (2 * ((size_t)(k >> 1) * NCOLS + j) + (k & 1))
                                 : ((size_t)j * nnz + k);
            pv2[slot] = make_uint2(0u, 0u);
        }
}

#define BUILD_BLOCKS (3 * NCOLS / 8)      // 3072 (8 warps per block)
#define TRANS_BLOCKS ((ROWS * IN_DIM + 255) / 256)

__global__ void prep_all(const float* __restrict__ x, float* __restrict__ xT,
                         const void* m1, const float* __restrict__ w1,
                         const void* m2, const float* __restrict__ w2,
                         const void* m3, const float* __restrict__ w3,
                         uint2* pv1, uint2* pv2, uint2* pv3, int* nz) {
    if (blockIdx.x < BUILD_BLOCKS) {
        int warp = blockIdx.x * 8 + (threadIdx.x >> 5);
        int lane = threadIdx.x & 31;
        int layer = warp >> 13;              // NCOLS = 2^13
        int j     = warp & (NCOLS - 1);
        int f = mask_flag(m1, lane);
        if (layer == 0)      build_one(m1, w1, pv1, j, lane, IN_DIM, NNZ1P, f, XSCALE, 0);
        else if (layer == 1) build_one(m2, w2, pv2, j, lane, HID,    NNZ2,  f, 1,      1);
        else                 build_one(m3, w3, pv3, j, lane, HID,    NNZ2,  f, 1,      1);
    } else if (blockIdx.x < BUILD_BLOCKS + TRANS_BLOCKS) {
        int u = (blockIdx.x - BUILD_BLOCKS) * 256 + threadIdx.x;
        if (u >= ROWS * IN_DIM) return;
        int row = u / IN_DIM;
        int i   = u - row * IN_DIM;
        int t   = row >> 6;
        int b   = row & 63;
        xT[(size_t)(row >> 5) * (IN_DIM * TB) + i * TB + (row & 31)] =
            x[(size_t)(b * T_STEPS + t) * IN_DIM + i];
    } else {
        for (int u = threadIdx.x; u < 3 * GROUPS; u += 256) nz[u] = 0;
    }
}

// ---------------- FUSED layer 1: sparse gemm + branch/membrane scan + spike ballot ----------------
// Block = 8 neurons (warps) x 32 batch lanes (one b-half). pv tile in smem once; x double-buffered per t.
__global__ __launch_bounds__(256)
void fused_layer1(const float* __restrict__ xT, const uint4* __restrict__ pv,
                  const float* __restrict__ bias, const float* __restrict__ tau_m,
                  const float* __restrict__ tau_n, unsigned* __restrict__ bitsOut,
                  int* __restrict__ nz) {
    __shared__ float s_x[2][IN_DIM * X2STR];    // 2 x 17.3KB
    __shared__ uint4 s_pv[64 * 8];              // 64 j x 8 uint4 (16 entries) = 8KB
    __shared__ float s_b[64];

    const int tid  = threadIdx.x;
    const int lane = tid & 31;
    const int w    = tid >> 5;                  // warp 0..7
    const int h0   = (blockIdx.x >> 1) * 8;
    const int hi   = blockIdx.x & 1;
    const int h    = h0 + w;

    // stage pv tile + bias (contiguous: j = h0*8 .. h0*8+64)
    {
        const uint4* src = pv + (size_t)h0 * 8 * K2_1;
        for (int u = tid; u < 64 * 8; u += 256) s_pv[u] = src[u];
        if (tid < 64) s_b[tid] = bias[h0 * 8 + tid];
    }

    // scan params (warp-broadcast loads)
    float beta[8], omb[8];
#pragma unroll
    for (int n = 0; n < 8; n++) {
        float bb = 1.f / (1.f + expf(-tau_n[h * 8 + n]));
        beta[n] = bb; omb[n] = 1.f - bb;
    }
    const float alpha = 1.f / (1.f + expf(-tau_m[h]));
    const float oma   = 1.f - alpha;

    float d[8];
#pragma unroll
    for (int n = 0; n < 8; n++) d[n] = 0.f;
    float mem = 0.f, spk = 0.f;

    // stage x slice for t=0 (group = t*2+hi): [120][32] -> [120][X2STR]
    {
        const float4* src4 = (const float4*)(xT + (size_t)hi * (IN_DIM * TB));
        for (int u4 = tid; u4 < IN_DIM * TB / 4; u4 += 256) {
            float4 v = src4[u4];
            int i  = u4 >> 3;
            int bq = (u4 & 7) << 2;
            *(float4*)(s_x[0] + i * X2STR + bq) = v;
        }
    }
    __syncthreads();

#pragma unroll 1
    for (int t = 0; t < T_STEPS; t++) {
        const int cur = t & 1;
        // prefetch next x slice into the other buffer
        if (t + 1 < T_STEPS) {
            const float4* src4 = (const float4*)(xT + (size_t)((t + 1) * 2 + hi) * (IN_DIM * TB));
            float* dst = s_x[cur ^ 1];
            for (int u4 = tid; u4 < IN_DIM * TB / 4; u4 += 256) {
                float4 v = src4[u4];
                int i  = u4 >> 3;
                int bq = (u4 & 7) << 2;
                *(float4*)(dst + i * X2STR + bq) = v;
            }
        }

        const char* xb = (const char*)s_x[cur] + lane * 4;   // idx pre-scaled to bytes
#pragma unroll
        for (int n = 0; n < 8; n++) {
            const uint4* e = s_pv + (w * 8 + n) * 8;
            float a0 = s_b[w * 8 + n], a1 = 0.f;
#pragma unroll
            for (int q = 0; q < 8; q++) {
                uint4 p = e[q];
                a0 += __uint_as_float(p.y) * *(const float*)(xb + p.x);
                a1 += __uint_as_float(p.w) * *(const float*)(xb + p.z);
            }
            d[n] = beta[n] * d[n] + omb[n] * (a0 + a1);
        }
        float l = ((d[0] + d[1]) + (d[2] + d[3])) + ((d[4] + d[5]) + (d[6] + d[7]));
        mem = mem * alpha + oma * l - spk;
        bool fired = mem > 1.0f;
        spk = fired ? 1.0f : 0.0f;
        unsigned bal = __ballot_sync(0xFFFFFFFFu, fired);
        if (lane == 0) {
            int grp = t * 2 + hi;
            bitsOut[(size_t)grp * HID + h] = bal;
            if (bal) nz[grp] = 1;
        }
        __syncthreads();
    }
}

// ---------------- layer-2/3 gemm: zero-flag groups do NOTHING (scan substitutes bias) ----------------
#define ADDS(MASK, V)                                   \
    _Pragma("unroll")                                   \
    for (int r = 0; r < 32; r++)                        \
        if ((MASK) & (1u << r)) acc[r] += (V);

__global__ __launch_bounds__(256)
void gemm_bits(const unsigned* __restrict__ bitsIn, const uint4* __restrict__ pv,
               const float* __restrict__ bias, float* __restrict__ D,
               const int* __restrict__ nz) {
    const int g = blockIdx.y;
    if (nz[g] == 0) return;                  // scan_sparse substitutes bias exactly

    __shared__ unsigned s_bits[HID];
    const int tid = threadIdx.x;
    const int j0  = blockIdx.x * 256 + tid;

    const unsigned* src = bitsIn + (size_t)g * HID;
    for (int u = tid; u < HID; u += 256) s_bits[u] = src[u];
    __syncthreads();

    float acc[32];
    {
        float bv = bias[j0];
#pragma unroll
        for (int r = 0; r < 32; r++) acc[r] = bv;
    }

    const uint4* base = pv + j0;
    uint4 s0 = base[(size_t)0 * NCOLS];
    uint4 s1 = base[(size_t)1 * NCOLS];
    uint4 s2 = base[(size_t)2 * NCOLS];
    uint4 s3 = base[(size_t)3 * NCOLS];
    unsigned mA0 = s_bits[s0.x], mA1 = s_bits[s0.z];
    unsigned mB0, mB1;

#pragma unroll 1
    for (int i = 0; i < K2_2; i += 4) {
        mB0 = s_bits[s1.x];  mB1 = s_bits[s1.z];
        {
            const float v0 = __uint_as_float(s0.y);
            const float v1 = __uint_as_float(s0.w);
            s0 = base[(size_t)min(i + 4, K2_2 - 1) * NCOLS];
            ADDS(mA0, v0);
            ADDS(mA1, v1);
        }
        mA0 = s_bits[s2.x];  mA1 = s_bits[s2.z];
        {
            const float v0 = __uint_as_float(s1.y);
            const float v1 = __uint_as_float(s1.w);
            s1 = base[(size_t)min(i + 5, K2_2 - 1) * NCOLS];
            ADDS(mB0, v0);
            ADDS(mB1, v1);
        }
        mB0 = s_bits[s3.x];  mB1 = s_bits[s3.z];
        {
            const float v0 = __uint_as_float(s2.y);
            const float v1 = __uint_as_float(s2.w);
            s2 = base[(size_t)min(i + 6, K2_2 - 1) * NCOLS];
            ADDS(mA0, v0);
            ADDS(mA1, v1);
        }
        mA0 = s_bits[s0.x];  mA1 = s_bits[s0.z];
        {
            const float v0 = __uint_as_float(s3.y);
            const float v1 = __uint_as_float(s3.w);
            s3 = base[(size_t)min(i + 7, K2_2 - 1) * NCOLS];
            ADDS(mB0, v0);
            ADDS(mB1, v1);
        }
    }

    float* dst = D + ((size_t)g * NCOLS + j0) * 32;
#pragma unroll
    for (int q = 0; q < 8; q++)
        *(float4*)(dst + q * 4) = make_float4(acc[q*4], acc[q*4+1], acc[q*4+2], acc[q*4+3]);
}

// ---------------- layer-2/3 scan: flag-aware (bias substitution; D read only if spikes) ----------------
__global__ __launch_bounds__(128)
void scan_sparse(const float* __restrict__ D, const float* __restrict__ bias,
                 const float* __restrict__ tau_m, const float* __restrict__ tau_n,
                 unsigned* __restrict__ bitsOut,
                 const int* __restrict__ nzIn, int* __restrict__ nzOut) {
    int tid  = blockIdx.x * 128 + threadIdx.x;
    int h    = tid >> 6;
    int b    = tid & 63;
    int hi   = b >> 5;
    int lane = threadIdx.x & 31;

    float beta[8], omb[8], bv[8];
#pragma unroll
    for (int n = 0; n < 8; n++) {
        float bb = 1.f / (1.f + expf(-tau_n[h * 8 + n]));
        beta[n] = bb; omb[n] = 1.f - bb;
        bv[n] = bias[h * 8 + n];
    }
    float alpha = 1.f / (1.f + expf(-tau_m[h]));
    float oma   = 1.f - alpha;

    float d[8];
#pragma unroll
    for (int n = 0; n < 8; n++) d[n] = 0.f;
    float mem = 0.f, spk = 0.f;

    const size_t tstride = (size_t)2 * NCOLS * 32;
    const float* dbase = D + ((size_t)hi * NCOLS + h * 8) * 32 + lane;

    int flag_next = nzIn[hi];                        // flag for t = 0

#pragma unroll 1
    for (int t = 0; t < T_STEPS; t++) {
        int flag = flag_next;
        if (t + 1 < T_STEPS) flag_next = nzIn[(t + 1) * 2 + hi];

        float q[8];
        if (flag) {                                  // warp-uniform branch (rare)
            const float* p = dbase + (size_t)t * tstride;
#pragma unroll
            for (int n = 0; n < 8; n++) q[n] = p[n * 32];
        } else {
#pragma unroll
            for (int n = 0; n < 8; n++) q[n] = bv[n];
        }
#pragma unroll
        for (int n = 0; n < 8; n++)
            d[n] = beta[n] * d[n] + omb[n] * q[n];
        float l = ((d[0] + d[1]) + (d[2] + d[3])) + ((d[4] + d[5]) + (d[6] + d[7]));
        mem = mem * alpha + oma * l - spk;
        bool fired = mem > 1.0f;
        spk = fired ? 1.0f : 0.0f;
        unsigned bal = __ballot_sync(0xFFFFFFFFu, fired);
        if (lane == 0) {
            int grp = t * 2 + hi;
            bitsOut[(size_t)grp * HID + h] = bal;
            if (bal) nzOut[grp] = 1;
        }
    }
}

// ---------------- readout from spike bitmasks (group-skip aware) ----------------
#define RO_THREADS 280          // 35 o x 8 chunks
__global__ __launch_bounds__(RO_THREADS)
void readout_bits(const unsigned* __restrict__ bitsIn, const float* __restrict__ wr,
                  const float* __restrict__ br, float* __restrict__ rOut,
                  const int* __restrict__ nz) {
    __shared__ unsigned s_bits[HID];
    __shared__ float    s_red[RO_THREADS * 32];
    const int tid = threadIdx.x;
    const int g   = blockIdx.x;

    if (nz[g] == 0) {
        for (int u = tid; u < OUT_DIM * 32; u += RO_THREADS) {
            int oo  = u >> 5;
            int row = u & 31;
            rOut[(size_t)(g * TB + row) * OUT_DIM + oo] = br[oo];
        }
        return;
    }

    const unsigned* src = bitsIn + (size_t)g * HID;
    for (int u = tid; u < HID; u += RO_THREADS) s_bits[u] = src[u];
    __syncthreads();

    const int o     = tid >> 3;
    const int chunk = tid & 7;
    float acc[32];
#pragma unroll
    for (int r = 0; r < 32; r++) acc[r] = 0.f;

    const float* wrow = wr + o * HID + chunk * 128;
    const unsigned* mb = s_bits + chunk * 128;
#pragma unroll 4
    for (int i = 0; i < 128; i++) {
        unsigned m = mb[i];
        float    v = wrow[i];
#pragma unroll
        for (int r = 0; r < 32; r++)
            if (m & (1u << r)) acc[r] += v;
    }
#pragma unroll
    for (int r = 0; r < 32; r++) s_red[tid * 32 + r] = acc[r];
    __syncthreads();

    for (int u = tid; u < OUT_DIM * 32; u += RO_THREADS) {
        int oo  = u >> 5;
        int row = u & 31;
        float s = br[oo];
#pragma unroll
        for (int c = 0; c < 8; c++)
            s += s_red[(oo * 8 + c) * 32 + row];
        rOut[(size_t)(g * TB + row) * OUT_DIM + oo] = s;
    }
}

// ---------------- readout leaky scan + mean + log_softmax ----------------
__global__ void final_k(const float* __restrict__ rIn, const float* __restrict__ tau_mr,
                        float* __restrict__ out) {
    int b = blockIdx.x;
    int o = threadIdx.x;                     // blockDim = 64, only o<35 active
    __shared__ float sv[64];
    __shared__ float s_mx, s_ls;
    float acc = 0.f;
    if (o < OUT_DIM) {
        float alpha = 1.f / (1.f + expf(-tau_mr[o]));
        float oma = 1.f - alpha;
        float mr = 0.f;
        for (int t = 0; t < T_STEPS; t++) {
            mr = mr * alpha + oma * rIn[(size_t)(t * 64 + b) * OUT_DIM + o];
            acc += mr;
        }
        acc /= (float)T_STEPS;
    }
    sv[o] = (o < OUT_DIM) ? acc : -1e30f;
    __syncthreads();
    if (o == 0) {
        float m = -1e30f;
        for (int i = 0; i < OUT_DIM; i++) m = fmaxf(m, sv[i]);
        float s = 0.f;
        for (int i = 0; i < OUT_DIM; i++) s += expf(sv[i] - m);
        s_mx = m; s_ls = logf(s);
    }
    __syncthreads();
    if (o < OUT_DIM) out[b * OUT_DIM + o] = sv[o] - s_mx - s_ls;
}

// ---------------- launch ----------------
extern "C" void kernel_launch(void* const* d_in, const int* in_sizes, int n_in,
                              void* d_out, int out_size) {
    (void)in_sizes; (void)n_in; (void)out_size;
    const float* x   = (const float*)d_in[0];
    const float* w1  = (const float*)d_in[1];
    const float* b1  = (const float*)d_in[2];
    const float* tm1 = (const float*)d_in[3];
    const float* tn1 = (const float*)d_in[4];
    const float* w2  = (const float*)d_in[5];
    const float* b2  = (const float*)d_in[6];
    const float* tm2 = (const float*)d_in[7];
    const float* tn2 = (const float*)d_in[8];
    const float* w3  = (const float*)d_in[9];
    const float* b3  = (const float*)d_in[10];
    const float* tm3 = (const float*)d_in[11];
    const float* tn3 = (const float*)d_in[12];
    const float* wr  = (const float*)d_in[13];
    const float* br  = (const float*)d_in[14];
    const float* tmr = (const float*)d_in[15];
    const void*  m1  = d_in[16];
    const void*  m2  = d_in[17];
    const void*  m3  = d_in[18];
    float* out = (float*)d_out;

    void *pD, *pB, *pxT, *pr, *pv1, *pv2, *pv3, *pnz;
    cudaGetSymbolAddress(&pD,  g_D);
    cudaGetSymbolAddress(&pB,  g_bits);
    cudaGetSymbolAddress(&pxT, g_xT);
    cudaGetSymbolAddress(&pr,  g_r);
    cudaGetSymbolAddress(&pv1, g_pv1);
    cudaGetSymbolAddress(&pv2, g_pv2);
    cudaGetSymbolAddress(&pv3, g_pv3);
    cudaGetSymbolAddress(&pnz, g_nz);

    int* nz = (int*)pnz;

    // 1) merged prep
    prep_all<<<BUILD_BLOCKS + TRANS_BLOCKS + 1, 256>>>(
        x, (float*)pxT, m1, w1, m2, w2, m3, w3,
        (uint2*)pv1, (uint2*)pv2, (uint2*)pv3, nz);

    dim3 gb(NCOLS / 256, GROUPS);
    const int scan_blocks = (BSZ * HID) / 128;

    // 2) layer 1 FUSED: gemm + scan -> bits + flags[0] (no D traffic)
    fused_layer1<<<256, 256>>>((const float*)pxT, (const uint4*)pv1, b1,
                               tm1, tn1, (unsigned*)pB, nz + 0 * GROUPS);

    // 3) layer 2: gemm only for spiking groups; flag-aware scan (bias substitution)
    gemm_bits<<<gb, 256>>>((const unsigned*)pB, (const uint4*)pv2, b2, (float*)pD, nz + 0 * GROUPS);
    scan_sparse<<<scan_blocks, 128>>>((const float*)pD, b2, tm2, tn2, (unsigned*)pB,
                                      nz + 0 * GROUPS, nz + 1 * GROUPS);

    // 4) layer 3: same
    gemm_bits<<<gb, 256>>>((const unsigned*)pB, (const uint4*)pv3, b3, (float*)pD, nz + 1 * GROUPS);
    scan_sparse<<<scan_blocks, 128>>>((const float*)pD, b3, tm3, tn3, (unsigned*)pB,
                                      nz + 1 * GROUPS, nz + 2 * GROUPS);

    // 5) readout from bits (skip zero groups) + final scan + log_softmax
    readout_bits<<<GROUPS, RO_THREADS>>>((const unsigned*)pB, wr, br, (float*)pr, nz + 2 * GROUPS);
    final_k<<<BSZ, 64>>>((const float*)pr, tmr, out);
}